// round 13
// baseline (speedup 1.0000x reference)
#include <cuda_runtime.h>
#include <cstdint>

#define NT 768
#define NG 3
#define NMI 64
#define NMA 16

// ---- weight region (float offsets, shared by all groups) ----
// WkT/WvT/WoT40/Wama40/Wami40/A68 hold PRE-CONVERTED tf32 bit patterns.
#define o_WqT    0
#define o_WkT    1024
#define o_WvT    2304
#define o_WoT40  3584
#define o_Wsma   4864
#define o_Wama40 5888
#define o_Wsmi40 7168
#define o_Wami40 8448
#define o_A68    9728
#define o_lng    14080
#define o_lnb    14112
#define o_bo     14144
#define o_bmi    14176
#define o_bma    14208
#define o_bqkv   14240
#define o_Ar     14336
#define W_FLOATS 14400

// ---- per-group state region ----
#define r_Sa    0
#define r_Sb    2560
#define r_Tmi   5120
#define r_Tma   6400
#define r_Ma    7552
#define r_Mb    8128
#define r_kpT   8704
#define r_vp    11008
#define r_mb    13568
#define ST_FLOATS 13696

#define SMEM_FLOATS (W_FLOATS + NG*ST_FLOATS)
#define SMEM_BYTES  (SMEM_FLOATS * 4)

__device__ __forceinline__ float warp_sum(float v) {
    #pragma unroll
    for (int o = 16; o; o >>= 1) v += __shfl_xor_sync(0xFFFFFFFFu, v, o);
    return v;
}
__device__ __forceinline__ float warp_max(float v) {
    #pragma unroll
    for (int o = 16; o; o >>= 1) v = fmaxf(v, __shfl_xor_sync(0xFFFFFFFFu, v, o));
    return v;
}
__device__ __forceinline__ void gbar(int wg) {
    asm volatile("bar.sync %0, 256;" :: "r"(wg + 1) : "memory");
}
__device__ __forceinline__ float4 ld4(const float* p) {
    return *reinterpret_cast<const float4*>(p);
}
__device__ __forceinline__ uint32_t f2tf(float x) {
    uint32_t r;
    asm("cvt.rna.tf32.f32 %0, %1;" : "=r"(r) : "f"(x));
    return r;
}
__device__ __forceinline__ float tfbits(float x) {   // tf32 bits stored as float
    return __uint_as_float(f2tf(x));
}
__device__ __forceinline__ uint32_t ldu(const float* p) {   // load pre-converted
    return __float_as_uint(*p);
}
__device__ __forceinline__ void mma_tf32(float* c,
    uint32_t a0, uint32_t a1, uint32_t a2, uint32_t a3,
    uint32_t b0, uint32_t b1)
{
    asm volatile(
        "mma.sync.aligned.m16n8k8.row.col.f32.tf32.tf32.f32 "
        "{%0,%1,%2,%3},{%4,%5,%6,%7},{%8,%9},{%0,%1,%2,%3};"
        : "+f"(c[0]), "+f"(c[1]), "+f"(c[2]), "+f"(c[3])
        : "r"(a0), "r"(a1), "r"(a2), "r"(a3), "r"(b0), "r"(b1));
}

__global__ __launch_bounds__(NT, 1)
void hm_kernel(
    const float* __restrict__ g_micro, const float* __restrict__ g_macro,
    const float* __restrict__ g_tmi,   const float* __restrict__ g_tma,
    const float* __restrict__ W_td,    const float* __restrict__ b_td,
    const float* __restrict__ ln_g,    const float* __restrict__ ln_b,
    const float* __restrict__ Wqkv,    const float* __restrict__ bqkv,
    const float* __restrict__ Wo,      const float* __restrict__ bo,
    const float* __restrict__ A_mi,    const float* __restrict__ Ws_mi,
    const float* __restrict__ Wa_mi,   const float* __restrict__ b_mi,
    const float* __restrict__ A_ma,    const float* __restrict__ Ws_ma,
    const float* __restrict__ Wa_ma,   const float* __restrict__ b_ma,
    const float* __restrict__ We1,     const float* __restrict__ be1,
    const float* __restrict__ We2,     const float* __restrict__ be2,
    const int*   __restrict__ steps_p,
    float* __restrict__ out, int B)
{
    extern __shared__ float sm[];
    const int tid   = threadIdx.x;
    const int lane  = tid & 31;
    const int wg    = tid >> 8;
    const int tid_g = tid & 255;
    const int warp  = tid_g >> 5;

    int b = blockIdx.x * NG + wg;
    const bool valid = (b < B);
    if (!valid) b = B - 1;

    // ---- stage weights (MMA-only operands pre-converted to tf32 bits) ----
    for (int i = tid; i < 1024; i += NT) {
        int d = i >> 5, e = i & 31;
        sm[o_WqT  + d*32 + e] = Wqkv[e*32 + d];
        sm[o_WkT  + d*40 + e] = tfbits(Wqkv[(32 + e)*32 + d]);
        sm[o_WvT  + d*40 + e] = tfbits(Wqkv[(64 + e)*32 + d]);
        sm[o_WoT40 + d*40 + e] = tfbits(Wo[e*32 + d]);
        sm[o_Wsma + i] = Ws_ma[i];
        sm[o_Wama40 + d*40 + e] = tfbits(Wa_ma[i]);
        sm[o_Wsmi40 + d*40 + e] = Ws_mi[i];
        sm[o_Wami40 + d*40 + e] = tfbits(Wa_mi[i]);
    }
    for (int i = tid; i < 4096; i += NT) {
        int r = i >> 6, c = i & 63;
        sm[o_A68 + r*68 + c] = tfbits(A_mi[i]);
    }
    if (tid < 32) {
        sm[o_lng + tid] = ln_g[tid];  sm[o_lnb + tid] = ln_b[tid];
        sm[o_bo  + tid] = bo[tid];
        sm[o_bmi + tid] = b_mi[tid];  sm[o_bma + tid] = b_ma[tid];
    }
    if (tid >= 32 && tid < 128) sm[o_bqkv + tid - 32] = bqkv[tid - 32];
    if (tid >= 128 && tid < 192) {               // A_mi row sums
        int m = tid - 128;
        float s = 0.f;
        #pragma unroll 8
        for (int n = 0; n < NMI; n++) s += A_mi[m*NMI + n];
        sm[o_Ar + m] = s;
    }

    // ---- stage per-group state ----
    float* st = sm + W_FLOATS + wg * ST_FLOATS;
    for (int i = tid_g; i < 2048; i += 256)
        st[r_Sa + (i >> 5)*40 + (i & 31)] = g_micro[(long long)b*2048 + i];
    for (int i = tid_g; i < 1024; i += 256) {
        st[r_Tmi + (i >> 5)*40 + (i & 31)] = g_tmi[(long long)b*1024 + i];
        st[r_Tma + (i >> 5)*36 + (i & 31)] = g_tma[(long long)b*1024 + i];
    }
    for (int i = tid_g; i < 512; i += 256)
        st[r_Ma + (i >> 5)*36 + (i & 31)] = g_macro[(long long)b*512 + i];

    const int steps = *steps_p;
    const float be2v = *be2;
    float* S   = st + r_Sa;  float* Sn = st + r_Sb;
    float* M   = st + r_Ma;  float* Mn = st + r_Mb;
    float* agg = st + r_kpT;        // stride-36 mma scratch / kpT / att
    float* kpT = st + r_kpT;
    float* wsc = st + r_kpT + 576;  // W'' tf32 bits, stride 40 (kpT dead then)
    float* qp  = st + r_Mb;         // alias: qp in Mb (dead C1..C3)
    float* vp  = st + r_vp;         // stride 40: W' tf32 (B-phase) / v tf32 (C-phase)
    float* mbuf = st + r_mb;        // [32..63] mb, [64..95] bw = b_mi + wdm
    __syncthreads();

    const int g = lane >> 2, t = lane & 3;

    // ---- prologue: A-phase for step 0 (mb/bw) + W' tf32 precompute ----
    if (tid_g < 32) {
        const int e = tid_g;
        float cm = 0.f;
        #pragma unroll
        for (int i = 0; i < NMA; i++) cm += M[i*36 + e];
        cm *= (1.f / NMA);
        float s = b_td[e];
        #pragma unroll
        for (int d4 = 0; d4 < 8; d4++) {
            float4 w = ld4(&W_td[e*32 + 4*d4]);
            s += w.x*__shfl_sync(0xFFFFFFFFu, cm, 4*d4+0)
               + w.y*__shfl_sync(0xFFFFFFFFu, cm, 4*d4+1)
               + w.z*__shfl_sync(0xFFFFFFFFu, cm, 4*d4+2)
               + w.w*__shfl_sync(0xFFFFFFFFu, cm, 4*d4+3);
        }
        float mbv = 0.1f * s;
        mbuf[32 + e] = mbv;
        float wd = 0.f;
        #pragma unroll 4
        for (int d = 0; d < 32; d++) {
            float md = __shfl_sync(0xFFFFFFFFu, mbv, d);
            wd += md * (sm[o_Wsmi40 + d*40 + e] + st[r_Tmi + d*40 + e]);
        }
        mbuf[64 + e] = wd + sm[o_bmi + e];
    }
    #pragma unroll
    for (int i = tid_g; i < 1024; i += 256) {
        int idx = (i >> 5)*40 + (i & 31);
        vp[idx] = tfbits(sm[o_Wsmi40 + idx] + st[r_Tmi + idx]);
    }
    gbar(wg);

    for (int it = 0; it < steps; ++it) {
        // ---- B1 (mma): agg = A_mi @ (S + mb), bias via row-sums of A ----
        {
            const int mt = warp & 3, h = warp >> 2;
            const int m0 = mt*16, n0 = h*16;
            float c0[4], c1[4];
            {
                float ar0 = sm[o_Ar + m0 + g], ar1 = sm[o_Ar + m0 + 8 + g];
                float2 mba = *(const float2*)&mbuf[32 + n0 + 2*t];
                float2 mbb = *(const float2*)&mbuf[32 + n0 + 8 + 2*t];
                c0[0]=ar0*mba.x; c0[1]=ar0*mba.y; c0[2]=ar1*mba.x; c0[3]=ar1*mba.y;
                c1[0]=ar0*mbb.x; c1[1]=ar0*mbb.y; c1[2]=ar1*mbb.x; c1[3]=ar1*mbb.y;
            }
            #pragma unroll
            for (int k0 = 0; k0 < 64; k0 += 8) {
                uint32_t a0 = ldu(&sm[o_A68 + (m0+g)*68   + k0 + t]);
                uint32_t a1 = ldu(&sm[o_A68 + (m0+8+g)*68 + k0 + t]);
                uint32_t a2 = ldu(&sm[o_A68 + (m0+g)*68   + k0 + 4 + t]);
                uint32_t a3 = ldu(&sm[o_A68 + (m0+8+g)*68 + k0 + 4 + t]);
                uint32_t b0 = f2tf(S[(k0+t)*40   + n0 + g]);
                uint32_t b1 = f2tf(S[(k0+t+4)*40 + n0 + g]);
                mma_tf32(c0, a0,a1,a2,a3, b0,b1);
                b0 = f2tf(S[(k0+t)*40   + n0 + 8 + g]);
                b1 = f2tf(S[(k0+t+4)*40 + n0 + 8 + g]);
                mma_tf32(c1, a0,a1,a2,a3, b0,b1);
            }
            *(float2*)&agg[(m0+g)*36   + n0 + 2*t]     = make_float2(c0[0], c0[1]);
            *(float2*)&agg[(m0+8+g)*36 + n0 + 2*t]     = make_float2(c0[2], c0[3]);
            *(float2*)&agg[(m0+g)*36   + n0 + 8 + 2*t] = make_float2(c1[0], c1[1]);
            *(float2*)&agg[(m0+8+g)*36 + n0 + 8 + 2*t] = make_float2(c1[2], c1[3]);
        }
        gbar(wg);

        // ---- B2+B3 (mma): update = tanh(agg@Wa + S@W' + bw); Sn = l2norm ----
        {
            const int mt = warp & 3, h = warp >> 2;
            const int m0 = mt*16, n0 = h*16;
            float c0[4] = {0,0,0,0}, c1[4] = {0,0,0,0};
            #pragma unroll
            for (int k0 = 0; k0 < 32; k0 += 8) {
                uint32_t a0 = f2tf(agg[(m0+g)*36   + k0 + t]);
                uint32_t a1 = f2tf(agg[(m0+8+g)*36 + k0 + t]);
                uint32_t a2 = f2tf(agg[(m0+g)*36   + k0 + 4 + t]);
                uint32_t a3 = f2tf(agg[(m0+8+g)*36 + k0 + 4 + t]);
                uint32_t b0 = ldu(&sm[o_Wami40 + (k0+t)*40   + n0 + g]);
                uint32_t b1 = ldu(&sm[o_Wami40 + (k0+t+4)*40 + n0 + g]);
                mma_tf32(c0, a0,a1,a2,a3, b0,b1);
                b0 = ldu(&sm[o_Wami40 + (k0+t)*40   + n0 + 8 + g]);
                b1 = ldu(&sm[o_Wami40 + (k0+t+4)*40 + n0 + 8 + g]);
                mma_tf32(c1, a0,a1,a2,a3, b0,b1);
                a0 = f2tf(S[(m0+g)*40   + k0 + t]);
                a1 = f2tf(S[(m0+8+g)*40 + k0 + t]);
                a2 = f2tf(S[(m0+g)*40   + k0 + 4 + t]);
                a3 = f2tf(S[(m0+8+g)*40 + k0 + 4 + t]);
                b0 = ldu(&vp[(k0+t)*40   + n0 + g]);
                b1 = ldu(&vp[(k0+t+4)*40 + n0 + g]);
                mma_tf32(c0, a0,a1,a2,a3, b0,b1);
                b0 = ldu(&vp[(k0+t)*40   + n0 + 8 + g]);
                b1 = ldu(&vp[(k0+t+4)*40 + n0 + 8 + g]);
                mma_tf32(c1, a0,a1,a2,a3, b0,b1);
            }
            float2 bw0 = *(const float2*)&mbuf[64 + n0 + 2*t];
            float2 bw1 = *(const float2*)&mbuf[64 + n0 + 8 + 2*t];
            float2 mb0 = *(const float2*)&mbuf[32 + n0 + 2*t];
            float2 mb1 = *(const float2*)&mbuf[32 + n0 + 8 + 2*t];
            float2 sA0 = *(const float2*)&S[(m0+g)*40   + n0 + 2*t];
            float2 sB0 = *(const float2*)&S[(m0+8+g)*40 + n0 + 2*t];
            float2 sA1 = *(const float2*)&S[(m0+g)*40   + n0 + 8 + 2*t];
            float2 sB1 = *(const float2*)&S[(m0+8+g)*40 + n0 + 8 + 2*t];
            float v00 = sA0.x + mb0.x + 0.1f*tanhf(c0[0] + bw0.x);
            float v01 = sA0.y + mb0.y + 0.1f*tanhf(c0[1] + bw0.y);
            float v02 = sB0.x + mb0.x + 0.1f*tanhf(c0[2] + bw0.x);
            float v03 = sB0.y + mb0.y + 0.1f*tanhf(c0[3] + bw0.y);
            float v10 = sA1.x + mb1.x + 0.1f*tanhf(c1[0] + bw1.x);
            float v11 = sA1.y + mb1.y + 0.1f*tanhf(c1[1] + bw1.y);
            float v12 = sB1.x + mb1.x + 0.1f*tanhf(c1[2] + bw1.x);
            float v13 = sB1.y + mb1.y + 0.1f*tanhf(c1[3] + bw1.y);
            float sqA = v00*v00 + v01*v01 + v10*v10 + v11*v11;
            float sqB = v02*v02 + v03*v03 + v12*v12 + v13*v13;
            sqA += __shfl_xor_sync(0xFFFFFFFFu, sqA, 1);
            sqA += __shfl_xor_sync(0xFFFFFFFFu, sqA, 2);
            sqB += __shfl_xor_sync(0xFFFFFFFFu, sqB, 1);
            sqB += __shfl_xor_sync(0xFFFFFFFFu, sqB, 2);
            float* rq = st + r_Mb;          // Mb dead during B-phase
            if (t == 0) {
                rq[h*64 + m0 + g]     = sqA;
                rq[h*64 + m0 + 8 + g] = sqB;
            }
            gbar(wg);
            float iA = 1.f / (sqrtf(rq[m0+g]     + rq[64 + m0+g])     + 1e-6f);
            float iB = 1.f / (sqrtf(rq[m0+8+g]   + rq[64 + m0+8+g])   + 1e-6f);
            *(float2*)&Sn[(m0+g)*40   + n0 + 2*t]     = make_float2(v00*iA, v01*iA);
            *(float2*)&Sn[(m0+8+g)*40 + n0 + 2*t]     = make_float2(v02*iB, v03*iB);
            *(float2*)&Sn[(m0+g)*40   + n0 + 8 + 2*t] = make_float2(v10*iA, v11*iA);
            *(float2*)&Sn[(m0+8+g)*40 + n0 + 8 + 2*t] = make_float2(v12*iB, v13*iB);
        }
        gbar(wg);

        // ---- B4 (mma, warps 0-3) ∥ C1 (warps 4-7): independent work ----
        if (warp < 4) {
            // Tmi = 0.95*Tmi + (0.05/64)*(S+mb)^T @ Sn
            const int m0 = (warp & 1) * 16, n0 = (warp >> 1) * 16;
            float c0[4] = {0,0,0,0}, c1[4] = {0,0,0,0};
            const float amb0 = mbuf[32 + m0 + g];
            const float amb1 = mbuf[32 + m0 + 8 + g];
            #pragma unroll
            for (int k0 = 0; k0 < 64; k0 += 8) {
                uint32_t a0 = f2tf(S[(k0+t)*40   + m0 + g]     + amb0);
                uint32_t a1 = f2tf(S[(k0+t)*40   + m0 + 8 + g] + amb1);
                uint32_t a2 = f2tf(S[(k0+t+4)*40 + m0 + g]     + amb0);
                uint32_t a3 = f2tf(S[(k0+t+4)*40 + m0 + 8 + g] + amb1);
                uint32_t b0 = f2tf(Sn[(k0+t)*40   + n0 + g]);
                uint32_t b1 = f2tf(Sn[(k0+t+4)*40 + n0 + g]);
                mma_tf32(c0, a0,a1,a2,a3, b0,b1);
                b0 = f2tf(Sn[(k0+t)*40   + n0 + 8 + g]);
                b1 = f2tf(Sn[(k0+t+4)*40 + n0 + 8 + g]);
                mma_tf32(c1, a0,a1,a2,a3, b0,b1);
            }
            const float scn = 0.05f / NMI;
            float2* p;
            p = (float2*)&st[r_Tmi + (m0+g)*40 + n0 + 2*t];
            *p = make_float2(0.95f*p->x + scn*c0[0], 0.95f*p->y + scn*c0[1]);
            p = (float2*)&st[r_Tmi + (m0+8+g)*40 + n0 + 2*t];
            *p = make_float2(0.95f*p->x + scn*c0[2], 0.95f*p->y + scn*c0[3]);
            p = (float2*)&st[r_Tmi + (m0+g)*40 + n0 + 8 + 2*t];
            *p = make_float2(0.95f*p->x + scn*c1[0], 0.95f*p->y + scn*c1[1]);
            p = (float2*)&st[r_Tmi + (m0+8+g)*40 + n0 + 8 + 2*t];
            *p = make_float2(0.95f*p->x + scn*c1[2], 0.95f*p->y + scn*c1[3]);
        } else {
            // C1: qp = M @ Wq.T + bq  (4 warps x 4 rows)
            const int w = warp - 4;
            float acc[4];
            #pragma unroll
            for (int j = 0; j < 4; j++) acc[j] = sm[o_bqkv + lane];
            #pragma unroll
            for (int d4 = 0; d4 < 8; d4++) {
                float q0 = sm[o_WqT + (4*d4+0)*32 + lane];
                float q1 = sm[o_WqT + (4*d4+1)*32 + lane];
                float q2 = sm[o_WqT + (4*d4+2)*32 + lane];
                float q3 = sm[o_WqT + (4*d4+3)*32 + lane];
                #pragma unroll
                for (int j = 0; j < 4; j++) {
                    float4 m4 = ld4(&M[(w*4+j)*36 + 4*d4]);
                    acc[j] += m4.x*q0 + m4.y*q1 + m4.z*q2 + m4.w*q3;
                }
            }
            #pragma unroll
            for (int j = 0; j < 4; j++) qp[(w*4+j)*32 + lane] = acc[j];
        }
        { float* tp = S; S = Sn; Sn = tp; }
        float* sc = Sn;                     // dead S buffer hosts softmax, stride 68
        gbar(wg);

        // ---- C2 (mma): kp/vp = S @ WkT/WvT + b (W pre-converted; vp stored tf32) ----
        {
            const int sel = warp >> 2;
            const int m0 = (warp & 3) * 16;
            const float* W = sel ? &sm[o_WvT] : &sm[o_WkT];
            const float* bias = &sm[o_bqkv + 32 + sel*32];
            float c[4][4];
            #pragma unroll
            for (int j = 0; j < 4; j++) {
                float b0v = bias[j*8 + 2*t], b1v = bias[j*8 + 2*t + 1];
                c[j][0] = b0v; c[j][1] = b1v; c[j][2] = b0v; c[j][3] = b1v;
            }
            #pragma unroll
            for (int k0 = 0; k0 < 32; k0 += 8) {
                uint32_t a0 = f2tf(S[(m0+g)*40   + k0 + t]);
                uint32_t a1 = f2tf(S[(m0+8+g)*40 + k0 + t]);
                uint32_t a2 = f2tf(S[(m0+g)*40   + k0 + 4 + t]);
                uint32_t a3 = f2tf(S[(m0+8+g)*40 + k0 + 4 + t]);
                #pragma unroll
                for (int j = 0; j < 4; j++) {
                    uint32_t b0 = ldu(&W[(k0+t)*40   + j*8 + g]);
                    uint32_t b1 = ldu(&W[(k0+t+4)*40 + j*8 + g]);
                    mma_tf32(c[j], a0,a1,a2,a3, b0,b1);
                }
            }
            if (sel == 0) {
                #pragma unroll
                for (int j = 0; j < 4; j++) {
                    kpT[(j*8 + 2*t)*65     + m0 + g]     = c[j][0];
                    kpT[(j*8 + 2*t + 1)*65 + m0 + g]     = c[j][1];
                    kpT[(j*8 + 2*t)*65     + m0 + 8 + g] = c[j][2];
                    kpT[(j*8 + 2*t + 1)*65 + m0 + 8 + g] = c[j][3];
                }
            } else {
                #pragma unroll
                for (int j = 0; j < 4; j++) {
                    *(float2*)&vp[(m0+g)*40   + j*8 + 2*t] =
                        make_float2(tfbits(c[j][0]), tfbits(c[j][1]));
                    *(float2*)&vp[(m0+8+g)*40 + j*8 + 2*t] =
                        make_float2(tfbits(c[j][2]), tfbits(c[j][3]));
                }
            }
        }
        gbar(wg);

        // ---- C3: scores + fused softmax (head-paired), sc stride 68 ----
        {
            #pragma unroll
            for (int h = 0; h < 2; h++) {
                float aA0 = 0.f, aA1 = 0.f, aB0 = 0.f, aB1 = 0.f;
                #pragma unroll
                for (int c = 0; c < 4; c++) {
                    int e = h*16 + 4*c;
                    float4 qa = ld4(&qp[warp*32 + e]);
                    float4 qb = ld4(&qp[(warp+8)*32 + e]);
                    float kA0 = kpT[(e+0)*65 + lane], kB0 = kpT[(e+0)*65 + lane + 32];
                    float kA1 = kpT[(e+1)*65 + lane], kB1 = kpT[(e+1)*65 + lane + 32];
                    float kA2 = kpT[(e+2)*65 + lane], kB2 = kpT[(e+2)*65 + lane + 32];
                    float kA3 = kpT[(e+3)*65 + lane], kB3 = kpT[(e+3)*65 + lane + 32];
                    aA0 += qa.x*kA0 + qa.y*kA1 + qa.z*kA2 + qa.w*kA3;
                    aA1 += qa.x*kB0 + qa.y*kB1 + qa.z*kB2 + qa.w*kB3;
                    aB0 += qb.x*kA0 + qb.y*kA1 + qb.z*kA2 + qb.w*kA3;
                    aB1 += qb.x*kB0 + qb.y*kB1 + qb.z*kB2 + qb.w*kB3;
                }
                aA0 *= 0.25f; aA1 *= 0.25f; aB0 *= 0.25f; aB1 *= 0.25f;
                {
                    int r = warp + 16*h;
                    float mx = warp_max(fmaxf(aA0, aA1));
                    float e0 = __expf(aA0 - mx), e1 = __expf(aA1 - mx);
                    float s = warp_sum(e0 + e1);
                    float inv = 1.f / s;
                    sc[r*68 + lane]      = e0 * inv;
                    sc[r*68 + lane + 32] = e1 * inv;
                }
                {
                    int r = warp + 8 + 16*h;
                    float mx = warp_max(fmaxf(aB0, aB1));
                    float e0 = __expf(aB0 - mx), e1 = __expf(aB1 - mx);
                    float s = warp_sum(e0 + e1);
                    float inv = 1.f / s;
                    sc[r*68 + lane]      = e0 * inv;
                    sc[r*68 + lane + 32] = e1 * inv;
                }
            }
        }
        gbar(wg);

        // ---- C4a (mma): att = sc @ vp per head (warps 0-3); W'' tf32 (4-7) ----
        if (warp < 4) {
            const int h = warp >> 1, nh = warp & 1;
            const int e0 = h*16 + nh*8;
            float c[4] = {0,0,0,0};
            #pragma unroll
            for (int k0 = 0; k0 < 64; k0 += 8) {
                uint32_t a0 = f2tf(sc[(h*16+g)*68   + k0 + t]);
                uint32_t a1 = f2tf(sc[(h*16+8+g)*68 + k0 + t]);
                uint32_t a2 = f2tf(sc[(h*16+g)*68   + k0 + 4 + t]);
                uint32_t a3 = f2tf(sc[(h*16+8+g)*68 + k0 + 4 + t]);
                uint32_t b0 = ldu(&vp[(k0+t)*40   + e0 + g]);
                uint32_t b1 = ldu(&vp[(k0+t+4)*40 + e0 + g]);
                mma_tf32(c, a0,a1,a2,a3, b0,b1);
            }
            *(float2*)&agg[g*36     + e0 + 2*t] = make_float2(c[0], c[1]);
            *(float2*)&agg[(g+8)*36 + e0 + 2*t] = make_float2(c[2], c[3]);
        } else {
            // W'' = tf32(Ws_ma + Tma) into kpT-region scratch (stride 40)
            for (int i = tid_g - 128; i < 1024; i += 128)
                wsc[(i >> 5)*40 + (i & 31)] = tfbits(sm[o_Wsma + i]
                                            + st[r_Tma + (i >> 5)*36 + (i & 31)]);
        }
        gbar(wg);

        // ---- C4b (mma): Mn = LN(M + agg@WoT + bo) ----
        {
            float x00, x01, x10, x11;
            const int n0 = (warp & 3) * 8;
            float* rqd = Sn;                 // dead softmax buffer
            if (warp < 4) {
                float c[4];
                {
                    float b0v = sm[o_bo + n0 + 2*t], b1v = sm[o_bo + n0 + 2*t + 1];
                    c[0] = b0v; c[1] = b1v; c[2] = b0v; c[3] = b1v;
                }
                #pragma unroll
                for (int k0 = 0; k0 < 32; k0 += 8) {
                    uint32_t a0 = f2tf(agg[g*36     + k0 + t]);
                    uint32_t a1 = f2tf(agg[(g+8)*36 + k0 + t]);
                    uint32_t a2 = f2tf(agg[g*36     + k0 + 4 + t]);
                    uint32_t a3 = f2tf(agg[(g+8)*36 + k0 + 4 + t]);
                    uint32_t b0 = ldu(&sm[o_WoT40 + (k0+t)*40   + n0 + g]);
                    uint32_t b1 = ldu(&sm[o_WoT40 + (k0+t+4)*40 + n0 + g]);
                    mma_tf32(c, a0,a1,a2,a3, b0,b1);
                }
                float2 m0v = *(const float2*)&M[g*36     + n0 + 2*t];
                float2 m1v = *(const float2*)&M[(g+8)*36 + n0 + 2*t];
                x00 = m0v.x + c[0]; x01 = m0v.y + c[1];
                x10 = m1v.x + c[2]; x11 = m1v.y + c[3];
                float sA = x00 + x01, qA = x00*x00 + x01*x01;
                float sB = x10 + x11, qB = x10*x10 + x11*x11;
                sA += __shfl_xor_sync(0xFFFFFFFFu, sA, 1);
                sA += __shfl_xor_sync(0xFFFFFFFFu, sA, 2);
                qA += __shfl_xor_sync(0xFFFFFFFFu, qA, 1);
                qA += __shfl_xor_sync(0xFFFFFFFFu, qA, 2);
                sB += __shfl_xor_sync(0xFFFFFFFFu, sB, 1);
                sB += __shfl_xor_sync(0xFFFFFFFFu, sB, 2);
                qB += __shfl_xor_sync(0xFFFFFFFFu, qB, 1);
                qB += __shfl_xor_sync(0xFFFFFFFFu, qB, 2);
                if (t == 0) {
                    rqd[warp*64 + g*2]         = sA;
                    rqd[warp*64 + g*2 + 1]     = qA;
                    rqd[warp*64 + (g+8)*2]     = sB;
                    rqd[warp*64 + (g+8)*2 + 1] = qB;
                }
            }
            gbar(wg);
            if (warp < 4) {
                float sxA = rqd[g*2]   + rqd[64 + g*2]   + rqd[128 + g*2]   + rqd[192 + g*2];
                float qxA = rqd[g*2+1] + rqd[64 + g*2+1] + rqd[128 + g*2+1] + rqd[192 + g*2+1];
                float sxB = rqd[(g+8)*2]   + rqd[64 + (g+8)*2]   + rqd[128 + (g+8)*2]   + rqd[192 + (g+8)*2];
                float qxB = rqd[(g+8)*2+1] + rqd[64 + (g+8)*2+1] + rqd[128 + (g+8)*2+1] + rqd[192 + (g+8)*2+1];
                float muA = sxA * (1.f/32.f);
                float muB = sxB * (1.f/32.f);
                float rA = rsqrtf(qxA*(1.f/32.f) - muA*muA + 1e-5f);
                float rB = rsqrtf(qxB*(1.f/32.f) - muB*muB + 1e-5f);
                float g0 = sm[o_lng + n0 + 2*t], g1 = sm[o_lng + n0 + 2*t + 1];
                float bb0 = sm[o_lnb + n0 + 2*t], bb1 = sm[o_lnb + n0 + 2*t + 1];
                *(float2*)&Mn[g*36 + n0 + 2*t] =
                    make_float2((x00-muA)*rA*g0 + bb0, (x01-muA)*rA*g1 + bb1);
                *(float2*)&Mn[(g+8)*36 + n0 + 2*t] =
                    make_float2((x10-muB)*rB*g0 + bb0, (x11-muB)*rB*g1 + bb1);
            }
        }
        gbar(wg);
        { float* tp = M; M = Mn; Mn = tp; }

        // ---- D1: macro agg = A_ma @ M (A_ma via LDG), agg stride 36 ----
        {
            float a0 = 0.f, a1 = 0.f;
            #pragma unroll
            for (int n4 = 0; n4 < 4; n4++) {
                float s0 = M[(4*n4+0)*36 + lane];
                float s1 = M[(4*n4+1)*36 + lane];
                float s2 = M[(4*n4+2)*36 + lane];
                float s3 = M[(4*n4+3)*36 + lane];
                float4 aa = ld4(&A_ma[warp*16 + 4*n4]);
                float4 ab = ld4(&A_ma[(warp+8)*16 + 4*n4]);
                a0 += aa.x*s0 + aa.y*s1 + aa.z*s2 + aa.w*s3;
                a1 += ab.x*s0 + ab.y*s1 + ab.z*s2 + ab.w*s3;
            }
            agg[warp*36 + lane] = a0;
            agg[(warp+8)*36 + lane] = a1;
        }
        gbar(wg);

        // ---- D2 (mma, warps 0-3) ∥ W'(next step) precompute (warps 4-7) ----
        {
            float v00, v01, v02, v03;
            const int n0 = (warp & 3) * 8;
            float* rqd = Sn;                 // dead sc buffer hosts row sums
            if (warp < 4) {
                float c[4];
                {
                    float b0v = sm[o_bma + n0 + 2*t], b1v = sm[o_bma + n0 + 2*t + 1];
                    c[0] = b0v; c[1] = b1v; c[2] = b0v; c[3] = b1v;
                }
                #pragma unroll
                for (int k0 = 0; k0 < 32; k0 += 8) {
                    uint32_t a0 = f2tf(agg[g*36     + k0 + t]);
                    uint32_t a1 = f2tf(agg[(g+8)*36 + k0 + t]);
                    uint32_t a2 = f2tf(agg[g*36     + k0 + 4 + t]);
                    uint32_t a3 = f2tf(agg[(g+8)*36 + k0 + 4 + t]);
                    uint32_t b0 = ldu(&sm[o_Wama40 + (k0+t)*40   + n0 + g]);
                    uint32_t b1 = ldu(&sm[o_Wama40 + (k0+t+4)*40 + n0 + g]);
                    mma_tf32(c, a0,a1,a2,a3, b0,b1);
                    a0 = f2tf(M[g*36     + k0 + t]);
                    a1 = f2tf(M[(g+8)*36 + k0 + t]);
                    a2 = f2tf(M[g*36     + k0 + 4 + t]);
                    a3 = f2tf(M[(g+8)*36 + k0 + 4 + t]);
                    b0 = ldu(&wsc[(k0+t)*40   + n0 + g]);
                    b1 = ldu(&wsc[(k0+t+4)*40 + n0 + g]);
                    mma_tf32(c, a0,a1,a2,a3, b0,b1);
                }
                float2 m0 = *(const float2*)&M[g*36     + n0 + 2*t];
                float2 m1 = *(const float2*)&M[(g+8)*36 + n0 + 2*t];
                v00 = m0.x + 0.1f*tanhf(c[0]);
                v01 = m0.y + 0.1f*tanhf(c[1]);
                v02 = m1.x + 0.1f*tanhf(c[2]);
                v03 = m1.y + 0.1f*tanhf(c[3]);
                float pA = v00*v00 + v01*v01;
                float pB = v02*v02 + v03*v03;
                pA += __shfl_xor_sync(0xFFFFFFFFu, pA, 1);
                pA += __shfl_xor_sync(0xFFFFFFFFu, pA, 2);
                pB += __shfl_xor_sync(0xFFFFFFFFu, pB, 1);
                pB += __shfl_xor_sync(0xFFFFFFFFu, pB, 2);
                if (t == 0) {
                    rqd[warp*16 + g]     = pA;
                    rqd[warp*16 + 8 + g] = pB;
                }
            } else {
                // W' = tf32(Ws_mi + Tmi) for next step (Tmi final since B4);
                // vp is dead (v consumed at C4a).
                for (int i = tid_g - 128; i < 1024; i += 128) {
                    int idx = (i >> 5)*40 + (i & 31);
                    vp[idx] = tfbits(sm[o_Wsmi40 + idx] + st[r_Tmi + idx]);
                }
            }
            gbar(wg);
            if (warp < 4) {
                float sA = rqd[g]      + rqd[16 + g]      + rqd[32 + g]      + rqd[48 + g];
                float sB = rqd[8 + g]  + rqd[24 + g]      + rqd[40 + g]      + rqd[56 + g];
                float iA = 1.f / (sqrtf(sA) + 1e-6f);
                float iB = 1.f / (sqrtf(sB) + 1e-6f);
                *(float2*)&Mn[g*36     + n0 + 2*t] = make_float2(v00*iA, v01*iA);
                *(float2*)&Mn[(g+8)*36 + n0 + 2*t] = make_float2(v02*iB, v03*iB);
            }
        }
        gbar(wg);

        // ---- D4 (mma, warps 0-3) ∥ A-phase for next step (warp 4) ----
        if (warp < 4) {
            // Tma = 0.95*Tma + (0.05/16)*M^T @ Mn
            const int m0 = (warp & 1) * 16, n0 = (warp >> 1) * 16;
            float c0[4] = {0,0,0,0}, c1[4] = {0,0,0,0};
            #pragma unroll
            for (int k0 = 0; k0 < 16; k0 += 8) {
                uint32_t a0 = f2tf(M[(k0+t)*36   + m0 + g]);
                uint32_t a1 = f2tf(M[(k0+t)*36   + m0 + 8 + g]);
                uint32_t a2 = f2tf(M[(k0+t+4)*36 + m0 + g]);
                uint32_t a3 = f2tf(M[(k0+t+4)*36 + m0 + 8 + g]);
                uint32_t b0 = f2tf(Mn[(k0+t)*36   + n0 + g]);
                uint32_t b1 = f2tf(Mn[(k0+t+4)*36 + n0 + g]);
                mma_tf32(c0, a0,a1,a2,a3, b0,b1);
                b0 = f2tf(Mn[(k0+t)*36   + n0 + 8 + g]);
                b1 = f2tf(Mn[(k0+t+4)*36 + n0 + 8 + g]);
                mma_tf32(c1, a0,a1,a2,a3, b0,b1);
            }
            const float scn = 0.05f / NMA;
            float2* p;
            p = (float2*)&st[r_Tma + (m0+g)*36 + n0 + 2*t];
            *p = make_float2(0.95f*p->x + scn*c0[0], 0.95f*p->y + scn*c0[1]);
            p = (float2*)&st[r_Tma + (m0+8+g)*36 + n0 + 2*t];
            *p = make_float2(0.95f*p->x + scn*c0[2], 0.95f*p->y + scn*c0[3]);
            p = (float2*)&st[r_Tma + (m0+g)*36 + n0 + 8 + 2*t];
            *p = make_float2(0.95f*p->x + scn*c1[0], 0.95f*p->y + scn*c1[1]);
            p = (float2*)&st[r_Tma + (m0+8+g)*36 + n0 + 8 + 2*t];
            *p = make_float2(0.95f*p->x + scn*c1[2], 0.95f*p->y + scn*c1[3]);
        } else if (warp == 4) {
            // A-phase for next step: mb/bw from the NEW macro (Mn = D2 output).
            const int e = lane;
            float cm = 0.f;
            #pragma unroll
            for (int i = 0; i < NMA; i++) cm += Mn[i*36 + e];
            cm *= (1.f / NMA);
            float s = b_td[e];
            #pragma unroll
            for (int d4 = 0; d4 < 8; d4++) {
                float4 w = ld4(&W_td[e*32 + 4*d4]);
                s += w.x*__shfl_sync(0xFFFFFFFFu, cm, 4*d4+0)
                   + w.y*__shfl_sync(0xFFFFFFFFu, cm, 4*d4+1)
                   + w.z*__shfl_sync(0xFFFFFFFFu, cm, 4*d4+2)
                   + w.w*__shfl_sync(0xFFFFFFFFu, cm, 4*d4+3);
            }
            float mbv = 0.1f * s;
            mbuf[32 + e] = mbv;
            float wd = 0.f;
            #pragma unroll 4
            for (int d = 0; d < 32; d++) {
                float md = __shfl_sync(0xFFFFFFFFu, mbv, d);
                wd += md * (sm[o_Wsmi40 + d*40 + e] + st[r_Tmi + d*40 + e]);
            }
            mbuf[64 + e] = wd + sm[o_bmi + e];
        }
        { float* tp = M; M = Mn; Mn = tp; }
        gbar(wg);
    }

    // ---- energy (final step only) ----
    {
        float* eb = st + r_Mb;
        for (int i = tid_g; i < 2048; i += 256) vp[i] = We1[i];
        if (tid_g < 64) { eb[tid_g] = be1[tid_g]; eb[64 + tid_g] = We2[tid_g]; }
        gbar(wg);

        float a0[8], a1[8];
        #pragma unroll
        for (int k = 0; k < 8; k++) { a0[k] = eb[lane]; a1[k] = eb[lane + 32]; }
        #pragma unroll 2
        for (int d4 = 0; d4 < 8; d4++) {
            float u0 = vp[(4*d4+0)*64 + lane];
            float u1 = vp[(4*d4+1)*64 + lane];
            float u2 = vp[(4*d4+2)*64 + lane];
            float u3 = vp[(4*d4+3)*64 + lane];
            float x0 = vp[(4*d4+0)*64 + lane + 32];
            float x1 = vp[(4*d4+1)*64 + lane + 32];
            float x2 = vp[(4*d4+2)*64 + lane + 32];
            float x3 = vp[(4*d4+3)*64 + lane + 32];
            #pragma unroll
            for (int k = 0; k < 8; k++) {
                float4 s4 = ld4(&S[(warp + 8*k)*40 + 4*d4]);
                a0[k] += s4.x*u0 + s4.y*u1 + s4.z*u2 + s4.w*u3;
                a1[k] += s4.x*x0 + s4.y*x1 + s4.z*x2 + s4.w*x3;
            }
        }
        float part = 0.f;
        #pragma unroll
        for (int k = 0; k < 8; k++)
            part += tanhf(a0[k]) * eb[64 + lane] + tanhf(a1[k]) * eb[96 + lane];
        part = warp_sum(part);
        if (lane == 0) eb[128 + warp] = part;
        gbar(wg);
        if (tid_g == 0) {
            float tot = 0.f;
            #pragma unroll
            for (int w = 0; w < 8; w++) tot += eb[128 + w];
            eb[144] = tot * (1.f / NMI) + be2v;
        }
        gbar(wg);
    }

    // ---- write outputs: micro | macro | tmi | tma | energy ----
    if (valid) {
        const long long off_macro = (long long)B * 2048;
        const long long off_tmi   = off_macro + (long long)B * 512;
        const long long off_tma   = off_tmi   + (long long)B * 1024;
        const long long off_en    = off_tma   + (long long)B * 1024;
        for (int i = tid_g; i < 2048; i += 256)
            out[(long long)b*2048 + i] = S[(i >> 5)*40 + (i & 31)];
        for (int i = tid_g; i < 512;  i += 256)
            out[off_macro + (long long)b*512 + i] = M[(i >> 5)*36 + (i & 31)];
        for (int i = tid_g; i < 1024; i += 256) {
            out[off_tmi + (long long)b*1024 + i] = st[r_Tmi + (i >> 5)*40 + (i & 31)];
            out[off_tma + (long long)b*1024 + i] = st[r_Tma + (i >> 5)*36 + (i & 31)];
        }
        if (tid_g == 0) out[off_en + b] = st[r_Mb + 144];
    }
}

extern "C" void kernel_launch(void* const* d_in, const int* in_sizes, int n_in,
                              void* d_out, int out_size)
{
    const int B = in_sizes[0] / (NMI * 32);
    cudaFuncSetAttribute(hm_kernel, cudaFuncAttributeMaxDynamicSharedMemorySize, SMEM_BYTES);
    hm_kernel<<<(B + NG - 1) / NG, NT, SMEM_BYTES>>>(
        (const float*)d_in[0],  (const float*)d_in[1],  (const float*)d_in[2],
        (const float*)d_in[3],  (const float*)d_in[4],  (const float*)d_in[5],
        (const float*)d_in[6],  (const float*)d_in[7],  (const float*)d_in[8],
        (const float*)d_in[9],  (const float*)d_in[10], (const float*)d_in[11],
        (const float*)d_in[12], (const float*)d_in[13], (const float*)d_in[14],
        (const float*)d_in[15], (const float*)d_in[16], (const float*)d_in[17],
        (const float*)d_in[18], (const float*)d_in[19], (const float*)d_in[20],
        (const float*)d_in[21], (const float*)d_in[22], (const float*)d_in[23],
        (const int*)d_in[24],
        (float*)d_out, B);
}

// round 14
// speedup vs baseline: 1.0208x; 1.0208x over previous
#include <cuda_runtime.h>
#include <cstdint>

#define NT 768
#define NG 3
#define NMI 64
#define NMA 16

// ---- weight region (float offsets, shared by all groups) ----
// WkT/WvT/WoT40/Wama40/Wami40/A68 hold PRE-CONVERTED tf32 bit patterns.
#define o_WqT    0
#define o_WkT    1024
#define o_WvT    2304
#define o_WoT40  3584
#define o_Wsma   4864
#define o_Wama40 5888
#define o_Wsmi40 7168
#define o_Wami40 8448
#define o_A68    9728
#define o_lng    14080
#define o_lnb    14112
#define o_bo     14144
#define o_bmi    14176
#define o_bma    14208
#define o_bqkv   14240
#define o_Ar     14336
#define W_FLOATS 14400

// ---- per-group state region ----
#define r_Sa    0
#define r_Sb    2560
#define r_Tmi   5120
#define r_Tma   6400
#define r_Ma    7552
#define r_Mb    8128
#define r_kpT   8704
#define r_vp    11008
#define r_mb    13568
#define ST_FLOATS 13696

#define SMEM_FLOATS (W_FLOATS + NG*ST_FLOATS)
#define SMEM_BYTES  (SMEM_FLOATS * 4)

__device__ __forceinline__ float warp_sum(float v) {
    #pragma unroll
    for (int o = 16; o; o >>= 1) v += __shfl_xor_sync(0xFFFFFFFFu, v, o);
    return v;
}
__device__ __forceinline__ float warp_max(float v) {
    #pragma unroll
    for (int o = 16; o; o >>= 1) v = fmaxf(v, __shfl_xor_sync(0xFFFFFFFFu, v, o));
    return v;
}
__device__ __forceinline__ void gbar(int wg) {
    asm volatile("bar.sync %0, 256;" :: "r"(wg + 1) : "memory");
}
__device__ __forceinline__ float4 ld4(const float* p) {
    return *reinterpret_cast<const float4*>(p);
}
__device__ __forceinline__ uint32_t f2tf(float x) {
    uint32_t r;
    asm("cvt.rna.tf32.f32 %0, %1;" : "=r"(r) : "f"(x));
    return r;
}
__device__ __forceinline__ float tfbits(float x) {   // tf32 bits stored as float
    return __uint_as_float(f2tf(x));
}
__device__ __forceinline__ uint32_t ldu(const float* p) {   // load pre-converted
    return __float_as_uint(*p);
}
__device__ __forceinline__ void mma_tf32(float* c,
    uint32_t a0, uint32_t a1, uint32_t a2, uint32_t a3,
    uint32_t b0, uint32_t b1)
{
    asm volatile(
        "mma.sync.aligned.m16n8k8.row.col.f32.tf32.tf32.f32 "
        "{%0,%1,%2,%3},{%4,%5,%6,%7},{%8,%9},{%0,%1,%2,%3};"
        : "+f"(c[0]), "+f"(c[1]), "+f"(c[2]), "+f"(c[3])
        : "r"(a0), "r"(a1), "r"(a2), "r"(a3), "r"(b0), "r"(b1));
}

__global__ __launch_bounds__(NT, 1)
void hm_kernel(
    const float* __restrict__ g_micro, const float* __restrict__ g_macro,
    const float* __restrict__ g_tmi,   const float* __restrict__ g_tma,
    const float* __restrict__ W_td,    const float* __restrict__ b_td,
    const float* __restrict__ ln_g,    const float* __restrict__ ln_b,
    const float* __restrict__ Wqkv,    const float* __restrict__ bqkv,
    const float* __restrict__ Wo,      const float* __restrict__ bo,
    const float* __restrict__ A_mi,    const float* __restrict__ Ws_mi,
    const float* __restrict__ Wa_mi,   const float* __restrict__ b_mi,
    const float* __restrict__ A_ma,    const float* __restrict__ Ws_ma,
    const float* __restrict__ Wa_ma,   const float* __restrict__ b_ma,
    const float* __restrict__ We1,     const float* __restrict__ be1,
    const float* __restrict__ We2,     const float* __restrict__ be2,
    const int*   __restrict__ steps_p,
    float* __restrict__ out, int B)
{
    extern __shared__ float sm[];
    const int tid   = threadIdx.x;
    const int lane  = tid & 31;
    const int wg    = tid >> 8;
    const int tid_g = tid & 255;
    const int warp  = tid_g >> 5;

    int b = blockIdx.x * NG + wg;
    const bool valid = (b < B);
    if (!valid) b = B - 1;

    // ---- stage weights (MMA-only operands pre-converted to tf32 bits) ----
    for (int i = tid; i < 1024; i += NT) {
        int d = i >> 5, e = i & 31;
        sm[o_WqT  + d*32 + e] = Wqkv[e*32 + d];
        sm[o_WkT  + d*40 + e] = tfbits(Wqkv[(32 + e)*32 + d]);
        sm[o_WvT  + d*40 + e] = tfbits(Wqkv[(64 + e)*32 + d]);
        sm[o_WoT40 + d*40 + e] = tfbits(Wo[e*32 + d]);
        sm[o_Wsma + i] = Ws_ma[i];
        sm[o_Wama40 + d*40 + e] = tfbits(Wa_ma[i]);
        sm[o_Wsmi40 + d*40 + e] = Ws_mi[i];
        sm[o_Wami40 + d*40 + e] = tfbits(Wa_mi[i]);
    }
    for (int i = tid; i < 4096; i += NT) {
        int r = i >> 6, c = i & 63;
        sm[o_A68 + r*68 + c] = tfbits(A_mi[i]);
    }
    if (tid < 32) {
        sm[o_lng + tid] = ln_g[tid];  sm[o_lnb + tid] = ln_b[tid];
        sm[o_bo  + tid] = bo[tid];
        sm[o_bmi + tid] = b_mi[tid];  sm[o_bma + tid] = b_ma[tid];
    }
    if (tid >= 32 && tid < 128) sm[o_bqkv + tid - 32] = bqkv[tid - 32];
    if (tid >= 128 && tid < 192) {               // A_mi row sums
        int m = tid - 128;
        float s = 0.f;
        #pragma unroll 8
        for (int n = 0; n < NMI; n++) s += A_mi[m*NMI + n];
        sm[o_Ar + m] = s;
    }

    // ---- stage per-group state ----
    float* st = sm + W_FLOATS + wg * ST_FLOATS;
    for (int i = tid_g; i < 2048; i += 256)
        st[r_Sa + (i >> 5)*40 + (i & 31)] = g_micro[(long long)b*2048 + i];
    for (int i = tid_g; i < 1024; i += 256) {
        st[r_Tmi + (i >> 5)*40 + (i & 31)] = g_tmi[(long long)b*1024 + i];
        st[r_Tma + (i >> 5)*36 + (i & 31)] = g_tma[(long long)b*1024 + i];
    }
    for (int i = tid_g; i < 512; i += 256)
        st[r_Ma + (i >> 5)*36 + (i & 31)] = g_macro[(long long)b*512 + i];

    const int steps = *steps_p;
    const float be2v = *be2;
    float* S   = st + r_Sa;  float* Sn = st + r_Sb;
    float* M   = st + r_Ma;  float* Mn = st + r_Mb;
    float* agg = st + r_kpT;        // stride-36 mma scratch / kpT / att
    float* kpT = st + r_kpT;
    float* wsc = st + r_kpT + 576;  // W'' tf32 bits, stride 40 (kpT dead then)
    float* qp  = st + r_Mb;         // alias: qp in Mb (dead C1..C3)
    float* vp  = st + r_vp;         // stride 40: W' tf32 (B-phase) / v tf32 (C-phase)
    float* mbuf = st + r_mb;        // [32..63] mb, [64..95] bw = b_mi + wdm
    __syncthreads();

    const int g = lane >> 2, t = lane & 3;

    for (int it = 0; it < steps; ++it) {
        // ---- A: macro bias mb + wdm/bw (warp 0); all warps: W' tf32 precompute ----
        if (tid_g < 32) {
            const int e = tid_g;
            float cm = 0.f;
            #pragma unroll
            for (int i = 0; i < NMA; i++) cm += M[i*36 + e];
            cm *= (1.f / NMA);
            float s = b_td[e];
            #pragma unroll
            for (int d4 = 0; d4 < 8; d4++) {
                float4 w = ld4(&W_td[e*32 + 4*d4]);
                s += w.x*__shfl_sync(0xFFFFFFFFu, cm, 4*d4+0)
                   + w.y*__shfl_sync(0xFFFFFFFFu, cm, 4*d4+1)
                   + w.z*__shfl_sync(0xFFFFFFFFu, cm, 4*d4+2)
                   + w.w*__shfl_sync(0xFFFFFFFFu, cm, 4*d4+3);
            }
            float mbv = 0.1f * s;
            mbuf[32 + e] = mbv;
            float wd = 0.f;
            #pragma unroll 4
            for (int d = 0; d < 32; d++) {
                float md = __shfl_sync(0xFFFFFFFFu, mbv, d);
                wd += md * (sm[o_Wsmi40 + d*40 + e] + st[r_Tmi + d*40 + e]);
            }
            mbuf[64 + e] = wd + sm[o_bmi + e];
        }
        // W' = tf32(Ws_mi + Tmi) into vp region (vp dead until C2 overwrites)
        #pragma unroll
        for (int i = tid_g; i < 1024; i += 256) {
            int idx = (i >> 5)*40 + (i & 31);
            vp[idx] = tfbits(sm[o_Wsmi40 + idx] + st[r_Tmi + idx]);
        }
        gbar(wg);

        // ---- B1 (mma): agg = A_mi @ (S + mb), bias via row-sums of A ----
        {
            const int mt = warp & 3, h = warp >> 2;
            const int m0 = mt*16, n0 = h*16;
            float c0[4], c1[4];
            {
                float ar0 = sm[o_Ar + m0 + g], ar1 = sm[o_Ar + m0 + 8 + g];
                float2 mba = *(const float2*)&mbuf[32 + n0 + 2*t];
                float2 mbb = *(const float2*)&mbuf[32 + n0 + 8 + 2*t];
                c0[0]=ar0*mba.x; c0[1]=ar0*mba.y; c0[2]=ar1*mba.x; c0[3]=ar1*mba.y;
                c1[0]=ar0*mbb.x; c1[1]=ar0*mbb.y; c1[2]=ar1*mbb.x; c1[3]=ar1*mbb.y;
            }
            #pragma unroll
            for (int k0 = 0; k0 < 64; k0 += 8) {
                uint32_t a0 = ldu(&sm[o_A68 + (m0+g)*68   + k0 + t]);
                uint32_t a1 = ldu(&sm[o_A68 + (m0+8+g)*68 + k0 + t]);
                uint32_t a2 = ldu(&sm[o_A68 + (m0+g)*68   + k0 + 4 + t]);
                uint32_t a3 = ldu(&sm[o_A68 + (m0+8+g)*68 + k0 + 4 + t]);
                uint32_t b0 = f2tf(S[(k0+t)*40   + n0 + g]);
                uint32_t b1 = f2tf(S[(k0+t+4)*40 + n0 + g]);
                mma_tf32(c0, a0,a1,a2,a3, b0,b1);
                b0 = f2tf(S[(k0+t)*40   + n0 + 8 + g]);
                b1 = f2tf(S[(k0+t+4)*40 + n0 + 8 + g]);
                mma_tf32(c1, a0,a1,a2,a3, b0,b1);
            }
            *(float2*)&agg[(m0+g)*36   + n0 + 2*t]     = make_float2(c0[0], c0[1]);
            *(float2*)&agg[(m0+8+g)*36 + n0 + 2*t]     = make_float2(c0[2], c0[3]);
            *(float2*)&agg[(m0+g)*36   + n0 + 8 + 2*t] = make_float2(c1[0], c1[1]);
            *(float2*)&agg[(m0+8+g)*36 + n0 + 8 + 2*t] = make_float2(c1[2], c1[3]);
        }
        gbar(wg);

        // ---- B2+B3 (mma): update = tanh(agg@Wa + S@W' + bw); Sn = l2norm ----
        {
            const int mt = warp & 3, h = warp >> 2;
            const int m0 = mt*16, n0 = h*16;
            float c0[4] = {0,0,0,0}, c1[4] = {0,0,0,0};
            #pragma unroll
            for (int k0 = 0; k0 < 32; k0 += 8) {
                uint32_t a0 = f2tf(agg[(m0+g)*36   + k0 + t]);
                uint32_t a1 = f2tf(agg[(m0+8+g)*36 + k0 + t]);
                uint32_t a2 = f2tf(agg[(m0+g)*36   + k0 + 4 + t]);
                uint32_t a3 = f2tf(agg[(m0+8+g)*36 + k0 + 4 + t]);
                uint32_t b0 = ldu(&sm[o_Wami40 + (k0+t)*40   + n0 + g]);
                uint32_t b1 = ldu(&sm[o_Wami40 + (k0+t+4)*40 + n0 + g]);
                mma_tf32(c0, a0,a1,a2,a3, b0,b1);
                b0 = ldu(&sm[o_Wami40 + (k0+t)*40   + n0 + 8 + g]);
                b1 = ldu(&sm[o_Wami40 + (k0+t+4)*40 + n0 + 8 + g]);
                mma_tf32(c1, a0,a1,a2,a3, b0,b1);
                a0 = f2tf(S[(m0+g)*40   + k0 + t]);
                a1 = f2tf(S[(m0+8+g)*40 + k0 + t]);
                a2 = f2tf(S[(m0+g)*40   + k0 + 4 + t]);
                a3 = f2tf(S[(m0+8+g)*40 + k0 + 4 + t]);
                b0 = ldu(&vp[(k0+t)*40   + n0 + g]);
                b1 = ldu(&vp[(k0+t+4)*40 + n0 + g]);
                mma_tf32(c0, a0,a1,a2,a3, b0,b1);
                b0 = ldu(&vp[(k0+t)*40   + n0 + 8 + g]);
                b1 = ldu(&vp[(k0+t+4)*40 + n0 + 8 + g]);
                mma_tf32(c1, a0,a1,a2,a3, b0,b1);
            }
            float2 bw0 = *(const float2*)&mbuf[64 + n0 + 2*t];
            float2 bw1 = *(const float2*)&mbuf[64 + n0 + 8 + 2*t];
            float2 mb0 = *(const float2*)&mbuf[32 + n0 + 2*t];
            float2 mb1 = *(const float2*)&mbuf[32 + n0 + 8 + 2*t];
            float2 sA0 = *(const float2*)&S[(m0+g)*40   + n0 + 2*t];
            float2 sB0 = *(const float2*)&S[(m0+8+g)*40 + n0 + 2*t];
            float2 sA1 = *(const float2*)&S[(m0+g)*40   + n0 + 8 + 2*t];
            float2 sB1 = *(const float2*)&S[(m0+8+g)*40 + n0 + 8 + 2*t];
            float v00 = sA0.x + mb0.x + 0.1f*tanhf(c0[0] + bw0.x);
            float v01 = sA0.y + mb0.y + 0.1f*tanhf(c0[1] + bw0.y);
            float v02 = sB0.x + mb0.x + 0.1f*tanhf(c0[2] + bw0.x);
            float v03 = sB0.y + mb0.y + 0.1f*tanhf(c0[3] + bw0.y);
            float v10 = sA1.x + mb1.x + 0.1f*tanhf(c1[0] + bw1.x);
            float v11 = sA1.y + mb1.y + 0.1f*tanhf(c1[1] + bw1.y);
            float v12 = sB1.x + mb1.x + 0.1f*tanhf(c1[2] + bw1.x);
            float v13 = sB1.y + mb1.y + 0.1f*tanhf(c1[3] + bw1.y);
            float sqA = v00*v00 + v01*v01 + v10*v10 + v11*v11;
            float sqB = v02*v02 + v03*v03 + v12*v12 + v13*v13;
            sqA += __shfl_xor_sync(0xFFFFFFFFu, sqA, 1);
            sqA += __shfl_xor_sync(0xFFFFFFFFu, sqA, 2);
            sqB += __shfl_xor_sync(0xFFFFFFFFu, sqB, 1);
            sqB += __shfl_xor_sync(0xFFFFFFFFu, sqB, 2);
            float* rq = st + r_Mb;          // Mb dead during B-phase
            if (t == 0) {
                rq[h*64 + m0 + g]     = sqA;
                rq[h*64 + m0 + 8 + g] = sqB;
            }
            gbar(wg);
            float iA = 1.f / (sqrtf(rq[m0+g]     + rq[64 + m0+g])     + 1e-6f);
            float iB = 1.f / (sqrtf(rq[m0+8+g]   + rq[64 + m0+8+g])   + 1e-6f);
            *(float2*)&Sn[(m0+g)*40   + n0 + 2*t]     = make_float2(v00*iA, v01*iA);
            *(float2*)&Sn[(m0+8+g)*40 + n0 + 2*t]     = make_float2(v02*iB, v03*iB);
            *(float2*)&Sn[(m0+g)*40   + n0 + 8 + 2*t] = make_float2(v10*iA, v11*iA);
            *(float2*)&Sn[(m0+8+g)*40 + n0 + 8 + 2*t] = make_float2(v12*iB, v13*iB);
        }
        gbar(wg);

        // ---- B4 (mma, warps 0-3) ∥ C1 (warps 4-7): independent work ----
        if (warp < 4) {
            // Tmi = 0.95*Tmi + (0.05/64)*(S+mb)^T @ Sn
            const int m0 = (warp & 1) * 16, n0 = (warp >> 1) * 16;
            float c0[4] = {0,0,0,0}, c1[4] = {0,0,0,0};
            const float amb0 = mbuf[32 + m0 + g];
            const float amb1 = mbuf[32 + m0 + 8 + g];
            #pragma unroll
            for (int k0 = 0; k0 < 64; k0 += 8) {
                uint32_t a0 = f2tf(S[(k0+t)*40   + m0 + g]     + amb0);
                uint32_t a1 = f2tf(S[(k0+t)*40   + m0 + 8 + g] + amb1);
                uint32_t a2 = f2tf(S[(k0+t+4)*40 + m0 + g]     + amb0);
                uint32_t a3 = f2tf(S[(k0+t+4)*40 + m0 + 8 + g] + amb1);
                uint32_t b0 = f2tf(Sn[(k0+t)*40   + n0 + g]);
                uint32_t b1 = f2tf(Sn[(k0+t+4)*40 + n0 + g]);
                mma_tf32(c0, a0,a1,a2,a3, b0,b1);
                b0 = f2tf(Sn[(k0+t)*40   + n0 + 8 + g]);
                b1 = f2tf(Sn[(k0+t+4)*40 + n0 + 8 + g]);
                mma_tf32(c1, a0,a1,a2,a3, b0,b1);
            }
            const float scn = 0.05f / NMI;
            float2* p;
            p = (float2*)&st[r_Tmi + (m0+g)*40 + n0 + 2*t];
            *p = make_float2(0.95f*p->x + scn*c0[0], 0.95f*p->y + scn*c0[1]);
            p = (float2*)&st[r_Tmi + (m0+8+g)*40 + n0 + 2*t];
            *p = make_float2(0.95f*p->x + scn*c0[2], 0.95f*p->y + scn*c0[3]);
            p = (float2*)&st[r_Tmi + (m0+g)*40 + n0 + 8 + 2*t];
            *p = make_float2(0.95f*p->x + scn*c1[0], 0.95f*p->y + scn*c1[1]);
            p = (float2*)&st[r_Tmi + (m0+8+g)*40 + n0 + 8 + 2*t];
            *p = make_float2(0.95f*p->x + scn*c1[2], 0.95f*p->y + scn*c1[3]);
        } else {
            // C1: qp = M @ Wq.T + bq  (4 warps x 4 rows; M untouched by B4)
            const int w = warp - 4;
            float acc[4];
            #pragma unroll
            for (int j = 0; j < 4; j++) acc[j] = sm[o_bqkv + lane];
            #pragma unroll
            for (int d4 = 0; d4 < 8; d4++) {
                float q0 = sm[o_WqT + (4*d4+0)*32 + lane];
                float q1 = sm[o_WqT + (4*d4+1)*32 + lane];
                float q2 = sm[o_WqT + (4*d4+2)*32 + lane];
                float q3 = sm[o_WqT + (4*d4+3)*32 + lane];
                #pragma unroll
                for (int j = 0; j < 4; j++) {
                    float4 m4 = ld4(&M[(w*4+j)*36 + 4*d4]);
                    acc[j] += m4.x*q0 + m4.y*q1 + m4.z*q2 + m4.w*q3;
                }
            }
            #pragma unroll
            for (int j = 0; j < 4; j++) qp[(w*4+j)*32 + lane] = acc[j];
        }
        { float* tp = S; S = Sn; Sn = tp; }
        float* sc = Sn;                     // dead S buffer hosts softmax, stride 68
        gbar(wg);

        // ---- C2 (mma): kp/vp = S @ WkT/WvT + b (W pre-converted; vp stored tf32) ----
        {
            const int sel = warp >> 2;
            const int m0 = (warp & 3) * 16;
            const float* W = sel ? &sm[o_WvT] : &sm[o_WkT];
            const float* bias = &sm[o_bqkv + 32 + sel*32];
            float c[4][4];
            #pragma unroll
            for (int j = 0; j < 4; j++) {
                float b0v = bias[j*8 + 2*t], b1v = bias[j*8 + 2*t + 1];
                c[j][0] = b0v; c[j][1] = b1v; c[j][2] = b0v; c[j][3] = b1v;
            }
            #pragma unroll
            for (int k0 = 0; k0 < 32; k0 += 8) {
                uint32_t a0 = f2tf(S[(m0+g)*40   + k0 + t]);
                uint32_t a1 = f2tf(S[(m0+8+g)*40 + k0 + t]);
                uint32_t a2 = f2tf(S[(m0+g)*40   + k0 + 4 + t]);
                uint32_t a3 = f2tf(S[(m0+8+g)*40 + k0 + 4 + t]);
                #pragma unroll
                for (int j = 0; j < 4; j++) {
                    uint32_t b0 = ldu(&W[(k0+t)*40   + j*8 + g]);
                    uint32_t b1 = ldu(&W[(k0+t+4)*40 + j*8 + g]);
                    mma_tf32(c[j], a0,a1,a2,a3, b0,b1);
                }
            }
            if (sel == 0) {
                #pragma unroll
                for (int j = 0; j < 4; j++) {
                    kpT[(j*8 + 2*t)*65     + m0 + g]     = c[j][0];
                    kpT[(j*8 + 2*t + 1)*65 + m0 + g]     = c[j][1];
                    kpT[(j*8 + 2*t)*65     + m0 + 8 + g] = c[j][2];
                    kpT[(j*8 + 2*t + 1)*65 + m0 + 8 + g] = c[j][3];
                }
            } else {
                #pragma unroll
                for (int j = 0; j < 4; j++) {
                    *(float2*)&vp[(m0+g)*40   + j*8 + 2*t] =
                        make_float2(tfbits(c[j][0]), tfbits(c[j][1]));
                    *(float2*)&vp[(m0+8+g)*40 + j*8 + 2*t] =
                        make_float2(tfbits(c[j][2]), tfbits(c[j][3]));
                }
            }
        }
        gbar(wg);

        // ---- C3: scores + fused softmax (head-paired), sc stride 68 ----
        {
            #pragma unroll
            for (int h = 0; h < 2; h++) {
                float aA0 = 0.f, aA1 = 0.f, aB0 = 0.f, aB1 = 0.f;
                #pragma unroll
                for (int c = 0; c < 4; c++) {
                    int e = h*16 + 4*c;
                    float4 qa = ld4(&qp[warp*32 + e]);
                    float4 qb = ld4(&qp[(warp+8)*32 + e]);
                    float kA0 = kpT[(e+0)*65 + lane], kB0 = kpT[(e+0)*65 + lane + 32];
                    float kA1 = kpT[(e+1)*65 + lane], kB1 = kpT[(e+1)*65 + lane + 32];
                    float kA2 = kpT[(e+2)*65 + lane], kB2 = kpT[(e+2)*65 + lane + 32];
                    float kA3 = kpT[(e+3)*65 + lane], kB3 = kpT[(e+3)*65 + lane + 32];
                    aA0 += qa.x*kA0 + qa.y*kA1 + qa.z*kA2 + qa.w*kA3;
                    aA1 += qa.x*kB0 + qa.y*kB1 + qa.z*kB2 + qa.w*kB3;
                    aB0 += qb.x*kA0 + qb.y*kA1 + qb.z*kA2 + qb.w*kA3;
                    aB1 += qb.x*kB0 + qb.y*kB1 + qb.z*kB2 + qb.w*kB3;
                }
                aA0 *= 0.25f; aA1 *= 0.25f; aB0 *= 0.25f; aB1 *= 0.25f;
                {
                    int r = warp + 16*h;
                    float mx = warp_max(fmaxf(aA0, aA1));
                    float e0 = __expf(aA0 - mx), e1 = __expf(aA1 - mx);
                    float s = warp_sum(e0 + e1);
                    float inv = 1.f / s;
                    sc[r*68 + lane]      = e0 * inv;
                    sc[r*68 + lane + 32] = e1 * inv;
                }
                {
                    int r = warp + 8 + 16*h;
                    float mx = warp_max(fmaxf(aB0, aB1));
                    float e0 = __expf(aB0 - mx), e1 = __expf(aB1 - mx);
                    float s = warp_sum(e0 + e1);
                    float inv = 1.f / s;
                    sc[r*68 + lane]      = e0 * inv;
                    sc[r*68 + lane + 32] = e1 * inv;
                }
            }
        }
        gbar(wg);

        // ---- C4a (mma): att = sc @ vp per head (warps 0-3); W'' tf32 (4-7) ----
        if (warp < 4) {
            const int h = warp >> 1, nh = warp & 1;
            const int e0 = h*16 + nh*8;
            float c[4] = {0,0,0,0};
            #pragma unroll
            for (int k0 = 0; k0 < 64; k0 += 8) {
                uint32_t a0 = f2tf(sc[(h*16+g)*68   + k0 + t]);
                uint32_t a1 = f2tf(sc[(h*16+8+g)*68 + k0 + t]);
                uint32_t a2 = f2tf(sc[(h*16+g)*68   + k0 + 4 + t]);
                uint32_t a3 = f2tf(sc[(h*16+8+g)*68 + k0 + 4 + t]);
                uint32_t b0 = ldu(&vp[(k0+t)*40   + e0 + g]);
                uint32_t b1 = ldu(&vp[(k0+t+4)*40 + e0 + g]);
                mma_tf32(c, a0,a1,a2,a3, b0,b1);
            }
            *(float2*)&agg[g*36     + e0 + 2*t] = make_float2(c[0], c[1]);
            *(float2*)&agg[(g+8)*36 + e0 + 2*t] = make_float2(c[2], c[3]);
        } else {
            // W'' = tf32(Ws_ma + Tma) into kpT-region scratch (stride 40)
            for (int i = tid_g - 128; i < 1024; i += 128)
                wsc[(i >> 5)*40 + (i & 31)] = tfbits(sm[o_Wsma + i]
                                            + st[r_Tma + (i >> 5)*36 + (i & 31)]);
        }
        gbar(wg);

        // ---- C4b (mma): Mn = LN(M + agg@WoT + bo) ----
        {
            float x00, x01, x10, x11;
            const int n0 = (warp & 3) * 8;
            float* rqd = Sn;                 // dead softmax buffer
            if (warp < 4) {
                float c[4];
                {
                    float b0v = sm[o_bo + n0 + 2*t], b1v = sm[o_bo + n0 + 2*t + 1];
                    c[0] = b0v; c[1] = b1v; c[2] = b0v; c[3] = b1v;
                }
                #pragma unroll
                for (int k0 = 0; k0 < 32; k0 += 8) {
                    uint32_t a0 = f2tf(agg[g*36     + k0 + t]);
                    uint32_t a1 = f2tf(agg[(g+8)*36 + k0 + t]);
                    uint32_t a2 = f2tf(agg[g*36     + k0 + 4 + t]);
                    uint32_t a3 = f2tf(agg[(g+8)*36 + k0 + 4 + t]);
                    uint32_t b0 = ldu(&sm[o_WoT40 + (k0+t)*40   + n0 + g]);
                    uint32_t b1 = ldu(&sm[o_WoT40 + (k0+t+4)*40 + n0 + g]);
                    mma_tf32(c, a0,a1,a2,a3, b0,b1);
                }
                float2 m0v = *(const float2*)&M[g*36     + n0 + 2*t];
                float2 m1v = *(const float2*)&M[(g+8)*36 + n0 + 2*t];
                x00 = m0v.x + c[0]; x01 = m0v.y + c[1];
                x10 = m1v.x + c[2]; x11 = m1v.y + c[3];
                float sA = x00 + x01, qA = x00*x00 + x01*x01;
                float sB = x10 + x11, qB = x10*x10 + x11*x11;
                sA += __shfl_xor_sync(0xFFFFFFFFu, sA, 1);
                sA += __shfl_xor_sync(0xFFFFFFFFu, sA, 2);
                qA += __shfl_xor_sync(0xFFFFFFFFu, qA, 1);
                qA += __shfl_xor_sync(0xFFFFFFFFu, qA, 2);
                sB += __shfl_xor_sync(0xFFFFFFFFu, sB, 1);
                sB += __shfl_xor_sync(0xFFFFFFFFu, sB, 2);
                qB += __shfl_xor_sync(0xFFFFFFFFu, qB, 1);
                qB += __shfl_xor_sync(0xFFFFFFFFu, qB, 2);
                if (t == 0) {
                    rqd[warp*64 + g*2]         = sA;
                    rqd[warp*64 + g*2 + 1]     = qA;
                    rqd[warp*64 + (g+8)*2]     = sB;
                    rqd[warp*64 + (g+8)*2 + 1] = qB;
                }
            }
            gbar(wg);
            if (warp < 4) {
                float sxA = rqd[g*2]   + rqd[64 + g*2]   + rqd[128 + g*2]   + rqd[192 + g*2];
                float qxA = rqd[g*2+1] + rqd[64 + g*2+1] + rqd[128 + g*2+1] + rqd[192 + g*2+1];
                float sxB = rqd[(g+8)*2]   + rqd[64 + (g+8)*2]   + rqd[128 + (g+8)*2]   + rqd[192 + (g+8)*2];
                float qxB = rqd[(g+8)*2+1] + rqd[64 + (g+8)*2+1] + rqd[128 + (g+8)*2+1] + rqd[192 + (g+8)*2+1];
                float muA = sxA * (1.f/32.f);
                float muB = sxB * (1.f/32.f);
                float rA = rsqrtf(qxA*(1.f/32.f) - muA*muA + 1e-5f);
                float rB = rsqrtf(qxB*(1.f/32.f) - muB*muB + 1e-5f);
                float g0 = sm[o_lng + n0 + 2*t], g1 = sm[o_lng + n0 + 2*t + 1];
                float bb0 = sm[o_lnb + n0 + 2*t], bb1 = sm[o_lnb + n0 + 2*t + 1];
                *(float2*)&Mn[g*36 + n0 + 2*t] =
                    make_float2((x00-muA)*rA*g0 + bb0, (x01-muA)*rA*g1 + bb1);
                *(float2*)&Mn[(g+8)*36 + n0 + 2*t] =
                    make_float2((x10-muB)*rB*g0 + bb0, (x11-muB)*rB*g1 + bb1);
            }
        }
        gbar(wg);
        { float* tp = M; M = Mn; Mn = tp; }

        // ---- D1: macro agg = A_ma @ M (A_ma via LDG), agg stride 36 ----
        {
            float a0 = 0.f, a1 = 0.f;
            #pragma unroll
            for (int n4 = 0; n4 < 4; n4++) {
                float s0 = M[(4*n4+0)*36 + lane];
                float s1 = M[(4*n4+1)*36 + lane];
                float s2 = M[(4*n4+2)*36 + lane];
                float s3 = M[(4*n4+3)*36 + lane];
                float4 aa = ld4(&A_ma[warp*16 + 4*n4]);
                float4 ab = ld4(&A_ma[(warp+8)*16 + 4*n4]);
                a0 += aa.x*s0 + aa.y*s1 + aa.z*s2 + aa.w*s3;
                a1 += ab.x*s0 + ab.y*s1 + ab.z*s2 + ab.w*s3;
            }
            agg[warp*36 + lane] = a0;
            agg[(warp+8)*36 + lane] = a1;
        }
        gbar(wg);

        // ---- D2 (mma): Mn = l2norm(M + 0.1*tanh(agg@Wama + M@W'' + bma)) ----
        {
            float v00, v01, v02, v03;
            const int n0 = (warp & 3) * 8;
            float* rqd = Sn;                 // dead sc buffer hosts row sums
            if (warp < 4) {
                float c[4];
                {
                    float b0v = sm[o_bma + n0 + 2*t], b1v = sm[o_bma + n0 + 2*t + 1];
                    c[0] = b0v; c[1] = b1v; c[2] = b0v; c[3] = b1v;
                }
                #pragma unroll
                for (int k0 = 0; k0 < 32; k0 += 8) {
                    uint32_t a0 = f2tf(agg[g*36     + k0 + t]);
                    uint32_t a1 = f2tf(agg[(g+8)*36 + k0 + t]);
                    uint32_t a2 = f2tf(agg[g*36     + k0 + 4 + t]);
                    uint32_t a3 = f2tf(agg[(g+8)*36 + k0 + 4 + t]);
                    uint32_t b0 = ldu(&sm[o_Wama40 + (k0+t)*40   + n0 + g]);
                    uint32_t b1 = ldu(&sm[o_Wama40 + (k0+t+4)*40 + n0 + g]);
                    mma_tf32(c, a0,a1,a2,a3, b0,b1);
                    a0 = f2tf(M[g*36     + k0 + t]);
                    a1 = f2tf(M[(g+8)*36 + k0 + t]);
                    a2 = f2tf(M[g*36     + k0 + 4 + t]);
                    a3 = f2tf(M[(g+8)*36 + k0 + 4 + t]);
                    b0 = ldu(&wsc[(k0+t)*40   + n0 + g]);
                    b1 = ldu(&wsc[(k0+t+4)*40 + n0 + g]);
                    mma_tf32(c, a0,a1,a2,a3, b0,b1);
                }
                float2 m0 = *(const float2*)&M[g*36     + n0 + 2*t];
                float2 m1 = *(const float2*)&M[(g+8)*36 + n0 + 2*t];
                v00 = m0.x + 0.1f*tanhf(c[0]);
                v01 = m0.y + 0.1f*tanhf(c[1]);
                v02 = m1.x + 0.1f*tanhf(c[2]);
                v03 = m1.y + 0.1f*tanhf(c[3]);
                float pA = v00*v00 + v01*v01;
                float pB = v02*v02 + v03*v03;
                pA += __shfl_xor_sync(0xFFFFFFFFu, pA, 1);
                pA += __shfl_xor_sync(0xFFFFFFFFu, pA, 2);
                pB += __shfl_xor_sync(0xFFFFFFFFu, pB, 1);
                pB += __shfl_xor_sync(0xFFFFFFFFu, pB, 2);
                if (t == 0) {
                    rqd[warp*16 + g]     = pA;
                    rqd[warp*16 + 8 + g] = pB;
                }
            }
            gbar(wg);
            if (warp < 4) {
                float sA = rqd[g]      + rqd[16 + g]      + rqd[32 + g]      + rqd[48 + g];
                float sB = rqd[8 + g]  + rqd[24 + g]      + rqd[40 + g]      + rqd[56 + g];
                float iA = 1.f / (sqrtf(sA) + 1e-6f);
                float iB = 1.f / (sqrtf(sB) + 1e-6f);
                *(float2*)&Mn[g*36     + n0 + 2*t] = make_float2(v00*iA, v01*iA);
                *(float2*)&Mn[(g+8)*36 + n0 + 2*t] = make_float2(v02*iB, v03*iB);
            }
        }
        gbar(wg);

        // ---- D4 (mma): Tma = 0.95*Tma + (0.05/16)*M^T @ Mn (stride-36 trace) ----
        if (warp < 4) {
            const int m0 = (warp & 1) * 16, n0 = (warp >> 1) * 16;
            float c0[4] = {0,0,0,0}, c1[4] = {0,0,0,0};
            #pragma unroll
            for (int k0 = 0; k0 < 16; k0 += 8) {
                uint32_t a0 = f2tf(M[(k0+t)*36   + m0 + g]);
                uint32_t a1 = f2tf(M[(k0+t)*36   + m0 + 8 + g]);
                uint32_t a2 = f2tf(M[(k0+t+4)*36 + m0 + g]);
                uint32_t a3 = f2tf(M[(k0+t+4)*36 + m0 + 8 + g]);
                uint32_t b0 = f2tf(Mn[(k0+t)*36   + n0 + g]);
                uint32_t b1 = f2tf(Mn[(k0+t+4)*36 + n0 + g]);
                mma_tf32(c0, a0,a1,a2,a3, b0,b1);
                b0 = f2tf(Mn[(k0+t)*36   + n0 + 8 + g]);
                b1 = f2tf(Mn[(k0+t+4)*36 + n0 + 8 + g]);
                mma_tf32(c1, a0,a1,a2,a3, b0,b1);
            }
            const float scn = 0.05f / NMA;
            float2* p;
            p = (float2*)&st[r_Tma + (m0+g)*36 + n0 + 2*t];
            *p = make_float2(0.95f*p->x + scn*c0[0], 0.95f*p->y + scn*c0[1]);
            p = (float2*)&st[r_Tma + (m0+8+g)*36 + n0 + 2*t];
            *p = make_float2(0.95f*p->x + scn*c0[2], 0.95f*p->y + scn*c0[3]);
            p = (float2*)&st[r_Tma + (m0+g)*36 + n0 + 8 + 2*t];
            *p = make_float2(0.95f*p->x + scn*c1[0], 0.95f*p->y + scn*c1[1]);
            p = (float2*)&st[r_Tma + (m0+8+g)*36 + n0 + 8 + 2*t];
            *p = make_float2(0.95f*p->x + scn*c1[2], 0.95f*p->y + scn*c1[3]);
        }
        { float* tp = M; M = Mn; Mn = tp; }
        gbar(wg);
    }

    // ---- energy (final step only) ----
    {
        float* eb = st + r_Mb;
        for (int i = tid_g; i < 2048; i += 256) vp[i] = We1[i];
        if (tid_g < 64) { eb[tid_g] = be1[tid_g]; eb[64 + tid_g] = We2[tid_g]; }
        gbar(wg);

        float a0[8], a1[8];
        #pragma unroll
        for (int k = 0; k < 8; k++) { a0[k] = eb[lane]; a1[k] = eb[lane + 32]; }
        #pragma unroll 2
        for (int d4 = 0; d4 < 8; d4++) {
            float u0 = vp[(4*d4+0)*64 + lane];
            float u1 = vp[(4*d4+1)*64 + lane];
            float u2 = vp[(4*d4+2)*64 + lane];
            float u3 = vp[(4*d4+3)*64 + lane];
            float x0 = vp[(4*d4+0)*64 + lane + 32];
            float x1 = vp[(4*d4+1)*64 + lane + 32];
            float x2 = vp[(4*d4+2)*64 + lane + 32];
            float x3 = vp[(4*d4+3)*64 + lane + 32];
            #pragma unroll
            for (int k = 0; k < 8; k++) {
                float4 s4 = ld4(&S[(warp + 8*k)*40 + 4*d4]);
                a0[k] += s4.x*u0 + s4.y*u1 + s4.z*u2 + s4.w*u3;
                a1[k] += s4.x*x0 + s4.y*x1 + s4.z*x2 + s4.w*x3;
            }
        }
        float part = 0.f;
        #pragma unroll
        for (int k = 0; k < 8; k++)
            part += tanhf(a0[k]) * eb[64 + lane] + tanhf(a1[k]) * eb[96 + lane];
        part = warp_sum(part);
        if (lane == 0) eb[128 + warp] = part;
        gbar(wg);
        if (tid_g == 0) {
            float tot = 0.f;
            #pragma unroll
            for (int w = 0; w < 8; w++) tot += eb[128 + w];
            eb[144] = tot * (1.f / NMI) + be2v;
        }
        gbar(wg);
    }

    // ---- write outputs: micro | macro | tmi | tma | energy ----
    if (valid) {
        const long long off_macro = (long long)B * 2048;
        const long long off_tmi   = off_macro + (long long)B * 512;
        const long long off_tma   = off_tmi   + (long long)B * 1024;
        const long long off_en    = off_tma   + (long long)B * 1024;
        for (int i = tid_g; i < 2048; i += 256)
            out[(long long)b*2048 + i] = S[(i >> 5)*40 + (i & 31)];
        for (int i = tid_g; i < 512;  i += 256)
            out[off_macro + (long long)b*512 + i] = M[(i >> 5)*36 + (i & 31)];
        for (int i = tid_g; i < 1024; i += 256) {
            out[off_tmi + (long long)b*1024 + i] = st[r_Tmi + (i >> 5)*40 + (i & 31)];
            out[off_tma + (long long)b*1024 + i] = st[r_Tma + (i >> 5)*36 + (i & 31)];
        }
        if (tid_g == 0) out[off_en + b] = st[r_Mb + 144];
    }
}

extern "C" void kernel_launch(void* const* d_in, const int* in_sizes, int n_in,
                              void* d_out, int out_size)
{
    const int B = in_sizes[0] / (NMI * 32);
    cudaFuncSetAttribute(hm_kernel, cudaFuncAttributeMaxDynamicSharedMemorySize, SMEM_BYTES);
    hm_kernel<<<(B + NG - 1) / NG, NT, SMEM_BYTES>>>(
        (const float*)d_in[0],  (const float*)d_in[1],  (const float*)d_in[2],
        (const float*)d_in[3],  (const float*)d_in[4],  (const float*)d_in[5],
        (const float*)d_in[6],  (const float*)d_in[7],  (const float*)d_in[8],
        (const float*)d_in[9],  (const float*)d_in[10], (const float*)d_in[11],
        (const float*)d_in[12], (const float*)d_in[13], (const float*)d_in[14],
        (const float*)d_in[15], (const float*)d_in[16], (const float*)d_in[17],
        (const float*)d_in[18], (const float*)d_in[19], (const float*)d_in[20],
        (const float*)d_in[21], (const float*)d_in[22], (const float*)d_in[23],
        (const int*)d_in[24],
        (float*)d_out, B);
}

// round 15
// speedup vs baseline: 1.0502x; 1.0288x over previous
#include <cuda_runtime.h>
#include <cstdint>

#define NT 768
#define NG 3
#define NMI 64
#define NMA 16

// ---- weight region (float offsets, shared by all groups) ----
// WkT/WvT/WoT40/Wama40/Wami40/A68 hold PRE-CONVERTED tf32 bit patterns.
#define o_WqT    0
#define o_WkT    1024
#define o_WvT    2304
#define o_WoT40  3584
#define o_Wsma   4864
#define o_Wama40 5888
#define o_Wsmi40 7168
#define o_Wami40 8448
#define o_A68    9728
#define o_lng    14080
#define o_lnb    14112
#define o_bo     14144
#define o_bmi    14176
#define o_bma    14208
#define o_bqkv   14240
#define o_Ar     14336
#define W_FLOATS 14400

// ---- per-group state region ----
#define r_Sa    0
#define r_Sb    2560
#define r_Tmi   5120
#define r_Tma   6400
#define r_Ma    7552
#define r_Mb    8128
#define r_kpT   8704
#define r_vp    11008
#define r_mb    13568
#define ST_FLOATS 13696

#define SMEM_FLOATS (W_FLOATS + NG*ST_FLOATS)
#define SMEM_BYTES  (SMEM_FLOATS * 4)

__device__ __forceinline__ float warp_sum(float v) {
    #pragma unroll
    for (int o = 16; o; o >>= 1) v += __shfl_xor_sync(0xFFFFFFFFu, v, o);
    return v;
}
__device__ __forceinline__ float warp_max(float v) {
    #pragma unroll
    for (int o = 16; o; o >>= 1) v = fmaxf(v, __shfl_xor_sync(0xFFFFFFFFu, v, o));
    return v;
}
__device__ __forceinline__ void gbar(int wg) {
    asm volatile("bar.sync %0, 256;" :: "r"(wg + 1) : "memory");
}
__device__ __forceinline__ float4 ld4(const float* p) {
    return *reinterpret_cast<const float4*>(p);
}
__device__ __forceinline__ uint32_t f2tf(float x) {
    uint32_t r;
    asm("cvt.rna.tf32.f32 %0, %1;" : "=r"(r) : "f"(x));
    return r;
}
__device__ __forceinline__ float tfbits(float x) {   // tf32 bits stored as float
    return __uint_as_float(f2tf(x));
}
__device__ __forceinline__ uint32_t ldu(const float* p) {   // load pre-converted
    return __float_as_uint(*p);
}
__device__ __forceinline__ void mma_tf32(float* c,
    uint32_t a0, uint32_t a1, uint32_t a2, uint32_t a3,
    uint32_t b0, uint32_t b1)
{
    asm volatile(
        "mma.sync.aligned.m16n8k8.row.col.f32.tf32.tf32.f32 "
        "{%0,%1,%2,%3},{%4,%5,%6,%7},{%8,%9},{%0,%1,%2,%3};"
        : "+f"(c[0]), "+f"(c[1]), "+f"(c[2]), "+f"(c[3])
        : "r"(a0), "r"(a1), "r"(a2), "r"(a3), "r"(b0), "r"(b1));
}

__global__ __launch_bounds__(NT, 1)
void hm_kernel(
    const float* __restrict__ g_micro, const float* __restrict__ g_macro,
    const float* __restrict__ g_tmi,   const float* __restrict__ g_tma,
    const float* __restrict__ W_td,    const float* __restrict__ b_td,
    const float* __restrict__ ln_g,    const float* __restrict__ ln_b,
    const float* __restrict__ Wqkv,    const float* __restrict__ bqkv,
    const float* __restrict__ Wo,      const float* __restrict__ bo,
    const float* __restrict__ A_mi,    const float* __restrict__ Ws_mi,
    const float* __restrict__ Wa_mi,   const float* __restrict__ b_mi,
    const float* __restrict__ A_ma,    const float* __restrict__ Ws_ma,
    const float* __restrict__ Wa_ma,   const float* __restrict__ b_ma,
    const float* __restrict__ We1,     const float* __restrict__ be1,
    const float* __restrict__ We2,     const float* __restrict__ be2,
    const int*   __restrict__ steps_p,
    float* __restrict__ out, int B)
{
    extern __shared__ float sm[];
    const int tid   = threadIdx.x;
    const int lane  = tid & 31;
    const int wg    = tid >> 8;
    const int tid_g = tid & 255;
    const int warp  = tid_g >> 5;

    int b = blockIdx.x * NG + wg;
    const bool valid = (b < B);
    if (!valid) b = B - 1;

    // ---- stage weights (MMA-only operands pre-converted to tf32 bits) ----
    for (int i = tid; i < 1024; i += NT) {
        int d = i >> 5, e = i & 31;
        sm[o_WqT  + d*32 + e] = Wqkv[e*32 + d];
        sm[o_WkT  + d*40 + e] = tfbits(Wqkv[(32 + e)*32 + d]);
        sm[o_WvT  + d*40 + e] = tfbits(Wqkv[(64 + e)*32 + d]);
        sm[o_WoT40 + d*40 + e] = tfbits(Wo[e*32 + d]);
        sm[o_Wsma + i] = Ws_ma[i];
        sm[o_Wama40 + d*40 + e] = tfbits(Wa_ma[i]);
        sm[o_Wsmi40 + d*40 + e] = Ws_mi[i];
        sm[o_Wami40 + d*40 + e] = tfbits(Wa_mi[i]);
    }
    for (int i = tid; i < 4096; i += NT) {
        int r = i >> 6, c = i & 63;
        sm[o_A68 + r*68 + c] = tfbits(A_mi[i]);
    }
    if (tid < 32) {
        sm[o_lng + tid] = ln_g[tid];  sm[o_lnb + tid] = ln_b[tid];
        sm[o_bo  + tid] = bo[tid];
        sm[o_bmi + tid] = b_mi[tid];  sm[o_bma + tid] = b_ma[tid];
    }
    if (tid >= 32 && tid < 128) sm[o_bqkv + tid - 32] = bqkv[tid - 32];
    if (tid >= 128 && tid < 192) {               // A_mi row sums
        int m = tid - 128;
        float s = 0.f;
        #pragma unroll 8
        for (int n = 0; n < NMI; n++) s += A_mi[m*NMI + n];
        sm[o_Ar + m] = s;
    }

    // ---- stage per-group state ----
    float* st = sm + W_FLOATS + wg * ST_FLOATS;
    for (int i = tid_g; i < 2048; i += 256)
        st[r_Sa + (i >> 5)*40 + (i & 31)] = g_micro[(long long)b*2048 + i];
    for (int i = tid_g; i < 1024; i += 256) {
        st[r_Tmi + (i >> 5)*40 + (i & 31)] = g_tmi[(long long)b*1024 + i];
        st[r_Tma + (i >> 5)*36 + (i & 31)] = g_tma[(long long)b*1024 + i];
    }
    for (int i = tid_g; i < 512; i += 256)
        st[r_Ma + (i >> 5)*36 + (i & 31)] = g_macro[(long long)b*512 + i];

    const int steps = *steps_p;
    const float be2v = *be2;
    float* S   = st + r_Sa;  float* Sn = st + r_Sb;
    float* M   = st + r_Ma;  float* Mn = st + r_Mb;
    float* agg = st + r_kpT;        // stride-36 mma scratch / kpT / att
    float* kpT = st + r_kpT;
    float* wsc = st + r_kpT + 576;  // W'' tf32 bits, stride 40 (kpT dead then)
    float* qp  = st + r_Mb;         // alias: qp in Mb (dead C1..C3)
    float* vp  = st + r_vp;         // stride 40: W' tf32 (B-phase) / v tf32 (C-phase)
    float* mbuf = st + r_mb;        // [32..63] mb, [64..95] bw = b_mi + wdm
    __syncthreads();

    const int g = lane >> 2, t = lane & 3;

    for (int it = 0; it < steps; ++it) {
        // ---- A: macro bias mb + wdm/bw (warp 0); all warps: W' tf32 precompute ----
        if (tid_g < 32) {
            const int e = tid_g;
            float cm = 0.f;
            #pragma unroll
            for (int i = 0; i < NMA; i++) cm += M[i*36 + e];
            cm *= (1.f / NMA);
            float s = b_td[e];
            #pragma unroll
            for (int d4 = 0; d4 < 8; d4++) {
                float4 w = ld4(&W_td[e*32 + 4*d4]);
                s += w.x*__shfl_sync(0xFFFFFFFFu, cm, 4*d4+0)
                   + w.y*__shfl_sync(0xFFFFFFFFu, cm, 4*d4+1)
                   + w.z*__shfl_sync(0xFFFFFFFFu, cm, 4*d4+2)
                   + w.w*__shfl_sync(0xFFFFFFFFu, cm, 4*d4+3);
            }
            float mbv = 0.1f * s;
            mbuf[32 + e] = mbv;
            float wd = 0.f;
            #pragma unroll 4
            for (int d = 0; d < 32; d++) {
                float md = __shfl_sync(0xFFFFFFFFu, mbv, d);
                wd += md * (sm[o_Wsmi40 + d*40 + e] + st[r_Tmi + d*40 + e]);
            }
            mbuf[64 + e] = wd + sm[o_bmi + e];
        }
        // W' = tf32(Ws_mi + Tmi) into vp region (vp dead until C2 overwrites)
        #pragma unroll
        for (int i = tid_g; i < 1024; i += 256) {
            int idx = (i >> 5)*40 + (i & 31);
            vp[idx] = tfbits(sm[o_Wsmi40 + idx] + st[r_Tmi + idx]);
        }
        gbar(wg);

        // ---- B1 (mma): agg = A_mi @ (S + mb); split-K accumulators (4-deep) ----
        {
            const int mt = warp & 3, h = warp >> 2;
            const int m0 = mt*16, n0 = h*16;
            float c0a[4], c1a[4], c0b[4] = {0,0,0,0}, c1b[4] = {0,0,0,0};
            {
                float ar0 = sm[o_Ar + m0 + g], ar1 = sm[o_Ar + m0 + 8 + g];
                float2 mba = *(const float2*)&mbuf[32 + n0 + 2*t];
                float2 mbb = *(const float2*)&mbuf[32 + n0 + 8 + 2*t];
                c0a[0]=ar0*mba.x; c0a[1]=ar0*mba.y; c0a[2]=ar1*mba.x; c0a[3]=ar1*mba.y;
                c1a[0]=ar0*mbb.x; c1a[1]=ar0*mbb.y; c1a[2]=ar1*mbb.x; c1a[3]=ar1*mbb.y;
            }
            #pragma unroll
            for (int k0 = 0; k0 < 64; k0 += 8) {
                float* c0 = (k0 < 32) ? c0a : c0b;
                float* c1 = (k0 < 32) ? c1a : c1b;
                uint32_t a0 = ldu(&sm[o_A68 + (m0+g)*68   + k0 + t]);
                uint32_t a1 = ldu(&sm[o_A68 + (m0+8+g)*68 + k0 + t]);
                uint32_t a2 = ldu(&sm[o_A68 + (m0+g)*68   + k0 + 4 + t]);
                uint32_t a3 = ldu(&sm[o_A68 + (m0+8+g)*68 + k0 + 4 + t]);
                uint32_t b0 = f2tf(S[(k0+t)*40   + n0 + g]);
                uint32_t b1 = f2tf(S[(k0+t+4)*40 + n0 + g]);
                mma_tf32(c0, a0,a1,a2,a3, b0,b1);
                b0 = f2tf(S[(k0+t)*40   + n0 + 8 + g]);
                b1 = f2tf(S[(k0+t+4)*40 + n0 + 8 + g]);
                mma_tf32(c1, a0,a1,a2,a3, b0,b1);
            }
            *(float2*)&agg[(m0+g)*36   + n0 + 2*t]     = make_float2(c0a[0]+c0b[0], c0a[1]+c0b[1]);
            *(float2*)&agg[(m0+8+g)*36 + n0 + 2*t]     = make_float2(c0a[2]+c0b[2], c0a[3]+c0b[3]);
            *(float2*)&agg[(m0+g)*36   + n0 + 8 + 2*t] = make_float2(c1a[0]+c1b[0], c1a[1]+c1b[1]);
            *(float2*)&agg[(m0+8+g)*36 + n0 + 8 + 2*t] = make_float2(c1a[2]+c1b[2], c1a[3]+c1b[3]);
        }
        gbar(wg);

        // ---- B2+B3 (mma): per-GEMM accumulators (4-deep chains) ----
        {
            const int mt = warp & 3, h = warp >> 2;
            const int m0 = mt*16, n0 = h*16;
            float c0w[4] = {0,0,0,0}, c1w[4] = {0,0,0,0};   // agg @ Wa_mi
            float c0s[4] = {0,0,0,0}, c1s[4] = {0,0,0,0};   // S @ W'
            #pragma unroll
            for (int k0 = 0; k0 < 32; k0 += 8) {
                uint32_t a0 = f2tf(agg[(m0+g)*36   + k0 + t]);
                uint32_t a1 = f2tf(agg[(m0+8+g)*36 + k0 + t]);
                uint32_t a2 = f2tf(agg[(m0+g)*36   + k0 + 4 + t]);
                uint32_t a3 = f2tf(agg[(m0+8+g)*36 + k0 + 4 + t]);
                uint32_t b0 = ldu(&sm[o_Wami40 + (k0+t)*40   + n0 + g]);
                uint32_t b1 = ldu(&sm[o_Wami40 + (k0+t+4)*40 + n0 + g]);
                mma_tf32(c0w, a0,a1,a2,a3, b0,b1);
                b0 = ldu(&sm[o_Wami40 + (k0+t)*40   + n0 + 8 + g]);
                b1 = ldu(&sm[o_Wami40 + (k0+t+4)*40 + n0 + 8 + g]);
                mma_tf32(c1w, a0,a1,a2,a3, b0,b1);
                a0 = f2tf(S[(m0+g)*40   + k0 + t]);
                a1 = f2tf(S[(m0+8+g)*40 + k0 + t]);
                a2 = f2tf(S[(m0+g)*40   + k0 + 4 + t]);
                a3 = f2tf(S[(m0+8+g)*40 + k0 + 4 + t]);
                b0 = ldu(&vp[(k0+t)*40   + n0 + g]);
                b1 = ldu(&vp[(k0+t+4)*40 + n0 + g]);
                mma_tf32(c0s, a0,a1,a2,a3, b0,b1);
                b0 = ldu(&vp[(k0+t)*40   + n0 + 8 + g]);
                b1 = ldu(&vp[(k0+t+4)*40 + n0 + 8 + g]);
                mma_tf32(c1s, a0,a1,a2,a3, b0,b1);
            }
            float c0[4], c1[4];
            #pragma unroll
            for (int j = 0; j < 4; j++) { c0[j] = c0w[j] + c0s[j]; c1[j] = c1w[j] + c1s[j]; }
            float2 bw0 = *(const float2*)&mbuf[64 + n0 + 2*t];
            float2 bw1 = *(const float2*)&mbuf[64 + n0 + 8 + 2*t];
            float2 mb0 = *(const float2*)&mbuf[32 + n0 + 2*t];
            float2 mb1 = *(const float2*)&mbuf[32 + n0 + 8 + 2*t];
            float2 sA0 = *(const float2*)&S[(m0+g)*40   + n0 + 2*t];
            float2 sB0 = *(const float2*)&S[(m0+8+g)*40 + n0 + 2*t];
            float2 sA1 = *(const float2*)&S[(m0+g)*40   + n0 + 8 + 2*t];
            float2 sB1 = *(const float2*)&S[(m0+8+g)*40 + n0 + 8 + 2*t];
            float v00 = sA0.x + mb0.x + 0.1f*tanhf(c0[0] + bw0.x);
            float v01 = sA0.y + mb0.y + 0.1f*tanhf(c0[1] + bw0.y);
            float v02 = sB0.x + mb0.x + 0.1f*tanhf(c0[2] + bw0.x);
            float v03 = sB0.y + mb0.y + 0.1f*tanhf(c0[3] + bw0.y);
            float v10 = sA1.x + mb1.x + 0.1f*tanhf(c1[0] + bw1.x);
            float v11 = sA1.y + mb1.y + 0.1f*tanhf(c1[1] + bw1.y);
            float v12 = sB1.x + mb1.x + 0.1f*tanhf(c1[2] + bw1.x);
            float v13 = sB1.y + mb1.y + 0.1f*tanhf(c1[3] + bw1.y);
            float sqA = v00*v00 + v01*v01 + v10*v10 + v11*v11;
            float sqB = v02*v02 + v03*v03 + v12*v12 + v13*v13;
            sqA += __shfl_xor_sync(0xFFFFFFFFu, sqA, 1);
            sqA += __shfl_xor_sync(0xFFFFFFFFu, sqA, 2);
            sqB += __shfl_xor_sync(0xFFFFFFFFu, sqB, 1);
            sqB += __shfl_xor_sync(0xFFFFFFFFu, sqB, 2);
            float* rq = st + r_Mb;          // Mb dead during B-phase
            if (t == 0) {
                rq[h*64 + m0 + g]     = sqA;
                rq[h*64 + m0 + 8 + g] = sqB;
            }
            gbar(wg);
            float iA = 1.f / (sqrtf(rq[m0+g]     + rq[64 + m0+g])     + 1e-6f);
            float iB = 1.f / (sqrtf(rq[m0+8+g]   + rq[64 + m0+8+g])   + 1e-6f);
            *(float2*)&Sn[(m0+g)*40   + n0 + 2*t]     = make_float2(v00*iA, v01*iA);
            *(float2*)&Sn[(m0+8+g)*40 + n0 + 2*t]     = make_float2(v02*iB, v03*iB);
            *(float2*)&Sn[(m0+g)*40   + n0 + 8 + 2*t] = make_float2(v10*iA, v11*iA);
            *(float2*)&Sn[(m0+8+g)*40 + n0 + 8 + 2*t] = make_float2(v12*iB, v13*iB);
        }
        gbar(wg);

        // ---- B4 (mma, warps 0-3) ∥ C1 (warps 4-7): independent work ----
        if (warp < 4) {
            // Tmi = 0.95*Tmi + (0.05/64)*(S+mb)^T @ Sn  (split-K, 4-deep)
            const int m0 = (warp & 1) * 16, n0 = (warp >> 1) * 16;
            float c0a[4] = {0,0,0,0}, c1a[4] = {0,0,0,0};
            float c0b[4] = {0,0,0,0}, c1b[4] = {0,0,0,0};
            const float amb0 = mbuf[32 + m0 + g];
            const float amb1 = mbuf[32 + m0 + 8 + g];
            #pragma unroll
            for (int k0 = 0; k0 < 64; k0 += 8) {
                float* c0 = (k0 < 32) ? c0a : c0b;
                float* c1 = (k0 < 32) ? c1a : c1b;
                uint32_t a0 = f2tf(S[(k0+t)*40   + m0 + g]     + amb0);
                uint32_t a1 = f2tf(S[(k0+t)*40   + m0 + 8 + g] + amb1);
                uint32_t a2 = f2tf(S[(k0+t+4)*40 + m0 + g]     + amb0);
                uint32_t a3 = f2tf(S[(k0+t+4)*40 + m0 + 8 + g] + amb1);
                uint32_t b0 = f2tf(Sn[(k0+t)*40   + n0 + g]);
                uint32_t b1 = f2tf(Sn[(k0+t+4)*40 + n0 + g]);
                mma_tf32(c0, a0,a1,a2,a3, b0,b1);
                b0 = f2tf(Sn[(k0+t)*40   + n0 + 8 + g]);
                b1 = f2tf(Sn[(k0+t+4)*40 + n0 + 8 + g]);
                mma_tf32(c1, a0,a1,a2,a3, b0,b1);
            }
            const float scn = 0.05f / NMI;
            float2* p;
            p = (float2*)&st[r_Tmi + (m0+g)*40 + n0 + 2*t];
            *p = make_float2(0.95f*p->x + scn*(c0a[0]+c0b[0]), 0.95f*p->y + scn*(c0a[1]+c0b[1]));
            p = (float2*)&st[r_Tmi + (m0+8+g)*40 + n0 + 2*t];
            *p = make_float2(0.95f*p->x + scn*(c0a[2]+c0b[2]), 0.95f*p->y + scn*(c0a[3]+c0b[3]));
            p = (float2*)&st[r_Tmi + (m0+g)*40 + n0 + 8 + 2*t];
            *p = make_float2(0.95f*p->x + scn*(c1a[0]+c1b[0]), 0.95f*p->y + scn*(c1a[1]+c1b[1]));
            p = (float2*)&st[r_Tmi + (m0+8+g)*40 + n0 + 8 + 2*t];
            *p = make_float2(0.95f*p->x + scn*(c1a[2]+c1b[2]), 0.95f*p->y + scn*(c1a[3]+c1b[3]));
        } else {
            // C1: qp = M @ Wq.T + bq  (4 warps x 4 rows; M untouched by B4)
            const int w = warp - 4;
            float acc[4];
            #pragma unroll
            for (int j = 0; j < 4; j++) acc[j] = sm[o_bqkv + lane];
            #pragma unroll
            for (int d4 = 0; d4 < 8; d4++) {
                float q0 = sm[o_WqT + (4*d4+0)*32 + lane];
                float q1 = sm[o_WqT + (4*d4+1)*32 + lane];
                float q2 = sm[o_WqT + (4*d4+2)*32 + lane];
                float q3 = sm[o_WqT + (4*d4+3)*32 + lane];
                #pragma unroll
                for (int j = 0; j < 4; j++) {
                    float4 m4 = ld4(&M[(w*4+j)*36 + 4*d4]);
                    acc[j] += m4.x*q0 + m4.y*q1 + m4.z*q2 + m4.w*q3;
                }
            }
            #pragma unroll
            for (int j = 0; j < 4; j++) qp[(w*4+j)*32 + lane] = acc[j];
        }
        { float* tp = S; S = Sn; Sn = tp; }
        float* sc = Sn;                     // dead S buffer hosts softmax, stride 68
        gbar(wg);

        // ---- C2 (mma): kp/vp = S @ WkT/WvT + b (W pre-converted; vp stored tf32) ----
        {
            const int sel = warp >> 2;
            const int m0 = (warp & 3) * 16;
            const float* W = sel ? &sm[o_WvT] : &sm[o_WkT];
            const float* bias = &sm[o_bqkv + 32 + sel*32];
            float c[4][4];
            #pragma unroll
            for (int j = 0; j < 4; j++) {
                float b0v = bias[j*8 + 2*t], b1v = bias[j*8 + 2*t + 1];
                c[j][0] = b0v; c[j][1] = b1v; c[j][2] = b0v; c[j][3] = b1v;
            }
            #pragma unroll
            for (int k0 = 0; k0 < 32; k0 += 8) {
                uint32_t a0 = f2tf(S[(m0+g)*40   + k0 + t]);
                uint32_t a1 = f2tf(S[(m0+8+g)*40 + k0 + t]);
                uint32_t a2 = f2tf(S[(m0+g)*40   + k0 + 4 + t]);
                uint32_t a3 = f2tf(S[(m0+8+g)*40 + k0 + 4 + t]);
                #pragma unroll
                for (int j = 0; j < 4; j++) {
                    uint32_t b0 = ldu(&W[(k0+t)*40   + j*8 + g]);
                    uint32_t b1 = ldu(&W[(k0+t+4)*40 + j*8 + g]);
                    mma_tf32(c[j], a0,a1,a2,a3, b0,b1);
                }
            }
            if (sel == 0) {
                #pragma unroll
                for (int j = 0; j < 4; j++) {
                    kpT[(j*8 + 2*t)*65     + m0 + g]     = c[j][0];
                    kpT[(j*8 + 2*t + 1)*65 + m0 + g]     = c[j][1];
                    kpT[(j*8 + 2*t)*65     + m0 + 8 + g] = c[j][2];
                    kpT[(j*8 + 2*t + 1)*65 + m0 + 8 + g] = c[j][3];
                }
            } else {
                #pragma unroll
                for (int j = 0; j < 4; j++) {
                    *(float2*)&vp[(m0+g)*40   + j*8 + 2*t] =
                        make_float2(tfbits(c[j][0]), tfbits(c[j][1]));
                    *(float2*)&vp[(m0+8+g)*40 + j*8 + 2*t] =
                        make_float2(tfbits(c[j][2]), tfbits(c[j][3]));
                }
            }
        }
        gbar(wg);

        // ---- C3: scores + fused softmax (head-paired), sc stride 68 ----
        {
            #pragma unroll
            for (int h = 0; h < 2; h++) {
                float aA0 = 0.f, aA1 = 0.f, aB0 = 0.f, aB1 = 0.f;
                #pragma unroll
                for (int c = 0; c < 4; c++) {
                    int e = h*16 + 4*c;
                    float4 qa = ld4(&qp[warp*32 + e]);
                    float4 qb = ld4(&qp[(warp+8)*32 + e]);
                    float kA0 = kpT[(e+0)*65 + lane], kB0 = kpT[(e+0)*65 + lane + 32];
                    float kA1 = kpT[(e+1)*65 + lane], kB1 = kpT[(e+1)*65 + lane + 32];
                    float kA2 = kpT[(e+2)*65 + lane], kB2 = kpT[(e+2)*65 + lane + 32];
                    float kA3 = kpT[(e+3)*65 + lane], kB3 = kpT[(e+3)*65 + lane + 32];
                    aA0 += qa.x*kA0 + qa.y*kA1 + qa.z*kA2 + qa.w*kA3;
                    aA1 += qa.x*kB0 + qa.y*kB1 + qa.z*kB2 + qa.w*kB3;
                    aB0 += qb.x*kA0 + qb.y*kA1 + qb.z*kA2 + qb.w*kA3;
                    aB1 += qb.x*kB0 + qb.y*kB1 + qb.z*kB2 + qb.w*kB3;
                }
                aA0 *= 0.25f; aA1 *= 0.25f; aB0 *= 0.25f; aB1 *= 0.25f;
                {
                    int r = warp + 16*h;
                    float mx = warp_max(fmaxf(aA0, aA1));
                    float e0 = __expf(aA0 - mx), e1 = __expf(aA1 - mx);
                    float s = warp_sum(e0 + e1);
                    float inv = 1.f / s;
                    sc[r*68 + lane]      = e0 * inv;
                    sc[r*68 + lane + 32] = e1 * inv;
                }
                {
                    int r = warp + 8 + 16*h;
                    float mx = warp_max(fmaxf(aB0, aB1));
                    float e0 = __expf(aB0 - mx), e1 = __expf(aB1 - mx);
                    float s = warp_sum(e0 + e1);
                    float inv = 1.f / s;
                    sc[r*68 + lane]      = e0 * inv;
                    sc[r*68 + lane + 32] = e1 * inv;
                }
            }
        }
        gbar(wg);

        // ---- C4a (mma): att = sc @ vp per head (warps 0-3); W'' tf32 (4-7) ----
        if (warp < 4) {
            const int h = warp >> 1, nh = warp & 1;
            const int e0 = h*16 + nh*8;
            float ca[4] = {0,0,0,0}, cb[4] = {0,0,0,0};
            #pragma unroll
            for (int k0 = 0; k0 < 64; k0 += 8) {
                float* c = (k0 < 32) ? ca : cb;
                uint32_t a0 = f2tf(sc[(h*16+g)*68   + k0 + t]);
                uint32_t a1 = f2tf(sc[(h*16+8+g)*68 + k0 + t]);
                uint32_t a2 = f2tf(sc[(h*16+g)*68   + k0 + 4 + t]);
                uint32_t a3 = f2tf(sc[(h*16+8+g)*68 + k0 + 4 + t]);
                uint32_t b0 = ldu(&vp[(k0+t)*40   + e0 + g]);
                uint32_t b1 = ldu(&vp[(k0+t+4)*40 + e0 + g]);
                mma_tf32(c, a0,a1,a2,a3, b0,b1);
            }
            *(float2*)&agg[g*36     + e0 + 2*t] = make_float2(ca[0]+cb[0], ca[1]+cb[1]);
            *(float2*)&agg[(g+8)*36 + e0 + 2*t] = make_float2(ca[2]+cb[2], ca[3]+cb[3]);
        } else {
            // W'' = tf32(Ws_ma + Tma) into kpT-region scratch (stride 40)
            for (int i = tid_g - 128; i < 1024; i += 128)
                wsc[(i >> 5)*40 + (i & 31)] = tfbits(sm[o_Wsma + i]
                                            + st[r_Tma + (i >> 5)*36 + (i & 31)]);
        }
        gbar(wg);

        // ---- C4b (mma): Mn = LN(M + agg@WoT + bo) ----
        {
            float x00, x01, x10, x11;
            const int n0 = (warp & 3) * 8;
            float* rqd = Sn;                 // dead softmax buffer
            if (warp < 4) {
                float c[4];
                {
                    float b0v = sm[o_bo + n0 + 2*t], b1v = sm[o_bo + n0 + 2*t + 1];
                    c[0] = b0v; c[1] = b1v; c[2] = b0v; c[3] = b1v;
                }
                #pragma unroll
                for (int k0 = 0; k0 < 32; k0 += 8) {
                    uint32_t a0 = f2tf(agg[g*36     + k0 + t]);
                    uint32_t a1 = f2tf(agg[(g+8)*36 + k0 + t]);
                    uint32_t a2 = f2tf(agg[g*36     + k0 + 4 + t]);
                    uint32_t a3 = f2tf(agg[(g+8)*36 + k0 + 4 + t]);
                    uint32_t b0 = ldu(&sm[o_WoT40 + (k0+t)*40   + n0 + g]);
                    uint32_t b1 = ldu(&sm[o_WoT40 + (k0+t+4)*40 + n0 + g]);
                    mma_tf32(c, a0,a1,a2,a3, b0,b1);
                }
                float2 m0v = *(const float2*)&M[g*36     + n0 + 2*t];
                float2 m1v = *(const float2*)&M[(g+8)*36 + n0 + 2*t];
                x00 = m0v.x + c[0]; x01 = m0v.y + c[1];
                x10 = m1v.x + c[2]; x11 = m1v.y + c[3];
                float sA = x00 + x01, qA = x00*x00 + x01*x01;
                float sB = x10 + x11, qB = x10*x10 + x11*x11;
                sA += __shfl_xor_sync(0xFFFFFFFFu, sA, 1);
                sA += __shfl_xor_sync(0xFFFFFFFFu, sA, 2);
                qA += __shfl_xor_sync(0xFFFFFFFFu, qA, 1);
                qA += __shfl_xor_sync(0xFFFFFFFFu, qA, 2);
                sB += __shfl_xor_sync(0xFFFFFFFFu, sB, 1);
                sB += __shfl_xor_sync(0xFFFFFFFFu, sB, 2);
                qB += __shfl_xor_sync(0xFFFFFFFFu, qB, 1);
                qB += __shfl_xor_sync(0xFFFFFFFFu, qB, 2);
                if (t == 0) {
                    rqd[warp*64 + g*2]         = sA;
                    rqd[warp*64 + g*2 + 1]     = qA;
                    rqd[warp*64 + (g+8)*2]     = sB;
                    rqd[warp*64 + (g+8)*2 + 1] = qB;
                }
            }
            gbar(wg);
            if (warp < 4) {
                float sxA = rqd[g*2]   + rqd[64 + g*2]   + rqd[128 + g*2]   + rqd[192 + g*2];
                float qxA = rqd[g*2+1] + rqd[64 + g*2+1] + rqd[128 + g*2+1] + rqd[192 + g*2+1];
                float sxB = rqd[(g+8)*2]   + rqd[64 + (g+8)*2]   + rqd[128 + (g+8)*2]   + rqd[192 + (g+8)*2];
                float qxB = rqd[(g+8)*2+1] + rqd[64 + (g+8)*2+1] + rqd[128 + (g+8)*2+1] + rqd[192 + (g+8)*2+1];
                float muA = sxA * (1.f/32.f);
                float muB = sxB * (1.f/32.f);
                float rA = rsqrtf(qxA*(1.f/32.f) - muA*muA + 1e-5f);
                float rB = rsqrtf(qxB*(1.f/32.f) - muB*muB + 1e-5f);
                float g0 = sm[o_lng + n0 + 2*t], g1 = sm[o_lng + n0 + 2*t + 1];
                float bb0 = sm[o_lnb + n0 + 2*t], bb1 = sm[o_lnb + n0 + 2*t + 1];
                *(float2*)&Mn[g*36 + n0 + 2*t] =
                    make_float2((x00-muA)*rA*g0 + bb0, (x01-muA)*rA*g1 + bb1);
                *(float2*)&Mn[(g+8)*36 + n0 + 2*t] =
                    make_float2((x10-muB)*rB*g0 + bb0, (x11-muB)*rB*g1 + bb1);
            }
        }
        gbar(wg);
        { float* tp = M; M = Mn; Mn = tp; }

        // ---- D1: macro agg = A_ma @ M (A_ma via LDG), agg stride 36 ----
        {
            float a0 = 0.f, a1 = 0.f;
            #pragma unroll
            for (int n4 = 0; n4 < 4; n4++) {
                float s0 = M[(4*n4+0)*36 + lane];
                float s1 = M[(4*n4+1)*36 + lane];
                float s2 = M[(4*n4+2)*36 + lane];
                float s3 = M[(4*n4+3)*36 + lane];
                float4 aa = ld4(&A_ma[warp*16 + 4*n4]);
                float4 ab = ld4(&A_ma[(warp+8)*16 + 4*n4]);
                a0 += aa.x*s0 + aa.y*s1 + aa.z*s2 + aa.w*s3;
                a1 += ab.x*s0 + ab.y*s1 + ab.z*s2 + ab.w*s3;
            }
            agg[warp*36 + lane] = a0;
            agg[(warp+8)*36 + lane] = a1;
        }
        gbar(wg);

        // ---- D2 (mma): per-GEMM accumulators (4-deep chains) ----
        {
            float v00, v01, v02, v03;
            const int n0 = (warp & 3) * 8;
            float* rqd = Sn;                 // dead sc buffer hosts row sums
            if (warp < 4) {
                float cw[4] = {0,0,0,0}, cs[4] = {0,0,0,0};
                #pragma unroll
                for (int k0 = 0; k0 < 32; k0 += 8) {
                    uint32_t a0 = f2tf(agg[g*36     + k0 + t]);
                    uint32_t a1 = f2tf(agg[(g+8)*36 + k0 + t]);
                    uint32_t a2 = f2tf(agg[g*36     + k0 + 4 + t]);
                    uint32_t a3 = f2tf(agg[(g+8)*36 + k0 + 4 + t]);
                    uint32_t b0 = ldu(&sm[o_Wama40 + (k0+t)*40   + n0 + g]);
                    uint32_t b1 = ldu(&sm[o_Wama40 + (k0+t+4)*40 + n0 + g]);
                    mma_tf32(cw, a0,a1,a2,a3, b0,b1);
                    a0 = f2tf(M[g*36     + k0 + t]);
                    a1 = f2tf(M[(g+8)*36 + k0 + t]);
                    a2 = f2tf(M[g*36     + k0 + 4 + t]);
                    a3 = f2tf(M[(g+8)*36 + k0 + 4 + t]);
                    b0 = ldu(&wsc[(k0+t)*40   + n0 + g]);
                    b1 = ldu(&wsc[(k0+t+4)*40 + n0 + g]);
                    mma_tf32(cs, a0,a1,a2,a3, b0,b1);
                }
                float c[4];
                {
                    float b0v = sm[o_bma + n0 + 2*t], b1v = sm[o_bma + n0 + 2*t + 1];
                    c[0] = cw[0] + cs[0] + b0v; c[1] = cw[1] + cs[1] + b1v;
                    c[2] = cw[2] + cs[2] + b0v; c[3] = cw[3] + cs[3] + b1v;
                }
                float2 m0 = *(const float2*)&M[g*36     + n0 + 2*t];
                float2 m1 = *(const float2*)&M[(g+8)*36 + n0 + 2*t];
                v00 = m0.x + 0.1f*tanhf(c[0]);
                v01 = m0.y + 0.1f*tanhf(c[1]);
                v02 = m1.x + 0.1f*tanhf(c[2]);
                v03 = m1.y + 0.1f*tanhf(c[3]);
                float pA = v00*v00 + v01*v01;
                float pB = v02*v02 + v03*v03;
                pA += __shfl_xor_sync(0xFFFFFFFFu, pA, 1);
                pA += __shfl_xor_sync(0xFFFFFFFFu, pA, 2);
                pB += __shfl_xor_sync(0xFFFFFFFFu, pB, 1);
                pB += __shfl_xor_sync(0xFFFFFFFFu, pB, 2);
                if (t == 0) {
                    rqd[warp*16 + g]     = pA;
                    rqd[warp*16 + 8 + g] = pB;
                }
            }
            gbar(wg);
            if (warp < 4) {
                float sA = rqd[g]      + rqd[16 + g]      + rqd[32 + g]      + rqd[48 + g];
                float sB = rqd[8 + g]  + rqd[24 + g]      + rqd[40 + g]      + rqd[56 + g];
                float iA = 1.f / (sqrtf(sA) + 1e-6f);
                float iB = 1.f / (sqrtf(sB) + 1e-6f);
                *(float2*)&Mn[g*36     + n0 + 2*t] = make_float2(v00*iA, v01*iA);
                *(float2*)&Mn[(g+8)*36 + n0 + 2*t] = make_float2(v02*iB, v03*iB);
            }
        }
        gbar(wg);

        // ---- D4 (mma): Tma = 0.95*Tma + (0.05/16)*M^T @ Mn (stride-36 trace) ----
        if (warp < 4) {
            const int m0 = (warp & 1) * 16, n0 = (warp >> 1) * 16;
            float c0[4] = {0,0,0,0}, c1[4] = {0,0,0,0};
            #pragma unroll
            for (int k0 = 0; k0 < 16; k0 += 8) {
                uint32_t a0 = f2tf(M[(k0+t)*36   + m0 + g]);
                uint32_t a1 = f2tf(M[(k0+t)*36   + m0 + 8 + g]);
                uint32_t a2 = f2tf(M[(k0+t+4)*36 + m0 + g]);
                uint32_t a3 = f2tf(M[(k0+t+4)*36 + m0 + 8 + g]);
                uint32_t b0 = f2tf(Mn[(k0+t)*36   + n0 + g]);
                uint32_t b1 = f2tf(Mn[(k0+t+4)*36 + n0 + g]);
                mma_tf32(c0, a0,a1,a2,a3, b0,b1);
                b0 = f2tf(Mn[(k0+t)*36   + n0 + 8 + g]);
                b1 = f2tf(Mn[(k0+t+4)*36 + n0 + 8 + g]);
                mma_tf32(c1, a0,a1,a2,a3, b0,b1);
            }
            const float scn = 0.05f / NMA;
            float2* p;
            p = (float2*)&st[r_Tma + (m0+g)*36 + n0 + 2*t];
            *p = make_float2(0.95f*p->x + scn*c0[0], 0.95f*p->y + scn*c0[1]);
            p = (float2*)&st[r_Tma + (m0+8+g)*36 + n0 + 2*t];
            *p = make_float2(0.95f*p->x + scn*c0[2], 0.95f*p->y + scn*c0[3]);
            p = (float2*)&st[r_Tma + (m0+g)*36 + n0 + 8 + 2*t];
            *p = make_float2(0.95f*p->x + scn*c1[0], 0.95f*p->y + scn*c1[1]);
            p = (float2*)&st[r_Tma + (m0+8+g)*36 + n0 + 8 + 2*t];
            *p = make_float2(0.95f*p->x + scn*c1[2], 0.95f*p->y + scn*c1[3]);
        }
        { float* tp = M; M = Mn; Mn = tp; }
        gbar(wg);
    }

    // ---- energy (final step only) ----
    {
        float* eb = st + r_Mb;
        for (int i = tid_g; i < 2048; i += 256) vp[i] = We1[i];
        if (tid_g < 64) { eb[tid_g] = be1[tid_g]; eb[64 + tid_g] = We2[tid_g]; }
        gbar(wg);

        float a0[8], a1[8];
        #pragma unroll
        for (int k = 0; k < 8; k++) { a0[k] = eb[lane]; a1[k] = eb[lane + 32]; }
        #pragma unroll 2
        for (int d4 = 0; d4 < 8; d4++) {
            float u0 = vp[(4*d4+0)*64 + lane];
            float u1 = vp[(4*d4+1)*64 + lane];
            float u2 = vp[(4*d4+2)*64 + lane];
            float u3 = vp[(4*d4+3)*64 + lane];
            float x0 = vp[(4*d4+0)*64 + lane + 32];
            float x1 = vp[(4*d4+1)*64 + lane + 32];
            float x2 = vp[(4*d4+2)*64 + lane + 32];
            float x3 = vp[(4*d4+3)*64 + lane + 32];
            #pragma unroll
            for (int k = 0; k < 8; k++) {
                float4 s4 = ld4(&S[(warp + 8*k)*40 + 4*d4]);
                a0[k] += s4.x*u0 + s4.y*u1 + s4.z*u2 + s4.w*u3;
                a1[k] += s4.x*x0 + s4.y*x1 + s4.z*x2 + s4.w*x3;
            }
        }
        float part = 0.f;
        #pragma unroll
        for (int k = 0; k < 8; k++)
            part += tanhf(a0[k]) * eb[64 + lane] + tanhf(a1[k]) * eb[96 + lane];
        part = warp_sum(part);
        if (lane == 0) eb[128 + warp] = part;
        gbar(wg);
        if (tid_g == 0) {
            float tot = 0.f;
            #pragma unroll
            for (int w = 0; w < 8; w++) tot += eb[128 + w];
            eb[144] = tot * (1.f / NMI) + be2v;
        }
        gbar(wg);
    }

    // ---- write outputs: micro | macro | tmi | tma | energy ----
    if (valid) {
        const long long off_macro = (long long)B * 2048;
        const long long off_tmi   = off_macro + (long long)B * 512;
        const long long off_tma   = off_tmi   + (long long)B * 1024;
        const long long off_en    = off_tma   + (long long)B * 1024;
        for (int i = tid_g; i < 2048; i += 256)
            out[(long long)b*2048 + i] = S[(i >> 5)*40 + (i & 31)];
        for (int i = tid_g; i < 512;  i += 256)
            out[off_macro + (long long)b*512 + i] = M[(i >> 5)*36 + (i & 31)];
        for (int i = tid_g; i < 1024; i += 256) {
            out[off_tmi + (long long)b*1024 + i] = st[r_Tmi + (i >> 5)*40 + (i & 31)];
            out[off_tma + (long long)b*1024 + i] = st[r_Tma + (i >> 5)*36 + (i & 31)];
        }
        if (tid_g == 0) out[off_en + b] = st[r_Mb + 144];
    }
}

extern "C" void kernel_launch(void* const* d_in, const int* in_sizes, int n_in,
                              void* d_out, int out_size)
{
    const int B = in_sizes[0] / (NMI * 32);
    cudaFuncSetAttribute(hm_kernel, cudaFuncAttributeMaxDynamicSharedMemorySize, SMEM_BYTES);
    hm_kernel<<<(B + NG - 1) / NG, NT, SMEM_BYTES>>>(
        (const float*)d_in[0],  (const float*)d_in[1],  (const float*)d_in[2],
        (const float*)d_in[3],  (const float*)d_in[4],  (const float*)d_in[5],
        (const float*)d_in[6],  (const float*)d_in[7],  (const float*)d_in[8],
        (const float*)d_in[9],  (const float*)d_in[10], (const float*)d_in[11],
        (const float*)d_in[12], (const float*)d_in[13], (const float*)d_in[14],
        (const float*)d_in[15], (const float*)d_in[16], (const float*)d_in[17],
        (const float*)d_in[18], (const float*)d_in[19], (const float*)d_in[20],
        (const float*)d_in[21], (const float*)d_in[22], (const float*)d_in[23],
        (const int*)d_in[24],
        (float*)d_out, B);
}